// round 1
// baseline (speedup 1.0000x reference)
#include <cuda_runtime.h>
#include <math.h>

// ---------------------------------------------------------------------------
// MambaBlock: B=2, L=2048, D_MODEL=768, D_INNER=1536, D_STATE=16, DT_RANK=48
// ---------------------------------------------------------------------------
#define BB   2
#define LL   2048
#define DM   768
#define DI   1536
#define NS   16
#define RK   48
#define MROWS (BB * LL)       // 4096
#define XP    80              // DT_RANK + 2*D_STATE

// ---------------- scratch (device globals; no allocation allowed) ----------
__device__ float g_xz  [MROWS * 2 * DI];   // in_proj output [4096, 3072]
__device__ float g_u   [MROWS * DI];       // conv+silu output
__device__ float g_xdbl[MROWS * XP];       // x_proj output [4096, 80]
__device__ float g_dt  [MROWS * DI];       // softplus(dt_proj)
__device__ float g_y   [MROWS * DI];       // scan output, gated
__device__ float g_ob  [MROWS * DM];       // out_proj output

// ---------------------------------------------------------------------------
// Generic C = A * B^T  (A: [M,K] row-major, B: [N,K] row-major, C: [M,N])
// 128x128x16 tile, 256 threads, 8x8 per thread.
// ---------------------------------------------------------------------------
__global__ void __launch_bounds__(256) sgemm_nt(
    const float* __restrict__ A, const float* __restrict__ B,
    float* __restrict__ C, int M, int N, int K)
{
    __shared__ float As[16][132];
    __shared__ float Bs[16][132];

    const int tid = threadIdx.x;
    const int bm = blockIdx.y * 128;
    const int bn = blockIdx.x * 128;
    const int tx = tid & 15;         // n dim
    const int ty = tid >> 4;         // m dim
    const int lr = tid >> 2;         // 0..63
    const int lc = (tid & 3) << 2;   // 0,4,8,12

    float acc[8][8];
#pragma unroll
    for (int i = 0; i < 8; ++i)
#pragma unroll
        for (int j = 0; j < 8; ++j) acc[i][j] = 0.f;

    for (int k0 = 0; k0 < K; k0 += 16) {
#pragma unroll
        for (int p = 0; p < 2; ++p) {
            int r = lr + p * 64;
            int gm = bm + r;
            float4 v = make_float4(0.f, 0.f, 0.f, 0.f);
            if (gm < M)
                v = *reinterpret_cast<const float4*>(A + (size_t)gm * K + k0 + lc);
            As[lc + 0][r] = v.x; As[lc + 1][r] = v.y;
            As[lc + 2][r] = v.z; As[lc + 3][r] = v.w;

            int gn = bn + r;
            float4 w = make_float4(0.f, 0.f, 0.f, 0.f);
            if (gn < N)
                w = *reinterpret_cast<const float4*>(B + (size_t)gn * K + k0 + lc);
            Bs[lc + 0][r] = w.x; Bs[lc + 1][r] = w.y;
            Bs[lc + 2][r] = w.z; Bs[lc + 3][r] = w.w;
        }
        __syncthreads();

#pragma unroll
        for (int k = 0; k < 16; ++k) {
            float ra[8], rb[8];
            *reinterpret_cast<float4*>(ra)     = *reinterpret_cast<const float4*>(&As[k][ty * 8]);
            *reinterpret_cast<float4*>(ra + 4) = *reinterpret_cast<const float4*>(&As[k][ty * 8 + 4]);
            *reinterpret_cast<float4*>(rb)     = *reinterpret_cast<const float4*>(&Bs[k][tx * 8]);
            *reinterpret_cast<float4*>(rb + 4) = *reinterpret_cast<const float4*>(&Bs[k][tx * 8 + 4]);
#pragma unroll
            for (int i = 0; i < 8; ++i)
#pragma unroll
                for (int j = 0; j < 8; ++j)
                    acc[i][j] = fmaf(ra[i], rb[j], acc[i][j]);
        }
        __syncthreads();
    }

#pragma unroll
    for (int i = 0; i < 8; ++i) {
        int gm = bm + ty * 8 + i;
        if (gm >= M) continue;
#pragma unroll
        for (int j = 0; j < 8; ++j) {
            int gn = bn + tx * 8 + j;
            if (gn < N) C[(size_t)gm * N + gn] = acc[i][j];
        }
    }
}

// ---------------------------------------------------------------------------
// Depthwise causal conv (k=4) + bias + silu over u = xz[:, :, 0:DI]
// ---------------------------------------------------------------------------
__global__ void __launch_bounds__(256) conv_silu_kernel(
    const float* __restrict__ conv_w, const float* __restrict__ conv_b)
{
    int idx = blockIdx.x * blockDim.x + threadIdx.x;
    if (idx >= MROWS * DI) return;
    int d = idx % DI;
    int l = (idx / DI) % LL;
    int b = idx / (DI * LL);

    float acc = conv_b[d];
#pragma unroll
    for (int j = 0; j < 4; ++j) {
        int ll = l - 3 + j;
        if (ll >= 0)
            acc = fmaf(conv_w[d * 4 + j],
                       g_xz[(size_t)(b * LL + ll) * (2 * DI) + d], acc);
    }
    // silu
    g_u[idx] = acc / (1.f + __expf(-acc));
}

// ---------------------------------------------------------------------------
// x_proj: x_dbl[4096,80] = u_act[4096,1536] * x_proj_w[80,1536]^T
// block: 32 rows x 80 cols, 256 threads, BK=32
// ---------------------------------------------------------------------------
__global__ void __launch_bounds__(256) gemm_xproj(
    const float* __restrict__ W)
{
    __shared__ float As[32][33];   // [k][m]
    __shared__ float Ws[32][81];   // [k][n]

    const int tid = threadIdx.x;
    const int m0 = blockIdx.x * 32;
    const int tx = tid & 15;       // n: 5 each
    const int ty = tid >> 4;       // m: 2 each

    float acc[2][5] = {};

    for (int k0 = 0; k0 < DI; k0 += 32) {
        for (int i = tid; i < 32 * 32; i += 256) {
            int m = i >> 5, k = i & 31;
            As[k][m] = g_u[(size_t)(m0 + m) * DI + k0 + k];
        }
        for (int i = tid; i < 80 * 32; i += 256) {
            int nn = i >> 5, k = i & 31;
            Ws[k][nn] = W[(size_t)nn * DI + k0 + k];
        }
        __syncthreads();
#pragma unroll
        for (int k = 0; k < 32; ++k) {
            float a0 = As[k][ty * 2];
            float a1 = As[k][ty * 2 + 1];
#pragma unroll
            for (int j = 0; j < 5; ++j) {
                float w = Ws[k][tx * 5 + j];
                acc[0][j] = fmaf(a0, w, acc[0][j]);
                acc[1][j] = fmaf(a1, w, acc[1][j]);
            }
        }
        __syncthreads();
    }
#pragma unroll
    for (int i = 0; i < 2; ++i)
#pragma unroll
        for (int j = 0; j < 5; ++j)
            g_xdbl[(size_t)(m0 + ty * 2 + i) * XP + tx * 5 + j] = acc[i][j];
}

// ---------------------------------------------------------------------------
// dt_proj (K=48) + bias + softplus
// block: 32 rows x 128 d, 256 threads
// ---------------------------------------------------------------------------
__global__ void __launch_bounds__(256) dtproj_softplus(
    const float* __restrict__ W, const float* __restrict__ bias)
{
    __shared__ float Ls[RK][33];    // dtl [r][m]
    __shared__ float Ws[RK][129];   // [r][d]

    const int tid = threadIdx.x;
    const int m0 = blockIdx.x * 32;
    const int d0 = blockIdx.y * 128;

    for (int i = tid; i < 32 * RK; i += 256) {
        int m = i / RK, r = i % RK;
        Ls[r][m] = g_xdbl[(size_t)(m0 + m) * XP + r];
    }
    for (int i = tid; i < 128 * RK; i += 256) {
        int d = i / RK, r = i % RK;
        Ws[r][d] = W[(size_t)(d0 + d) * RK + r];
    }
    __syncthreads();

    const int tx = tid & 15;   // d: 8 each
    const int ty = tid >> 4;   // m: 2 each
    float acc[2][8] = {};
#pragma unroll
    for (int r = 0; r < RK; ++r) {
        float a0 = Ls[r][ty * 2];
        float a1 = Ls[r][ty * 2 + 1];
#pragma unroll
        for (int j = 0; j < 8; ++j) {
            float w = Ws[r][tx * 8 + j];
            acc[0][j] = fmaf(a0, w, acc[0][j]);
            acc[1][j] = fmaf(a1, w, acc[1][j]);
        }
    }
#pragma unroll
    for (int i = 0; i < 2; ++i)
#pragma unroll
        for (int j = 0; j < 8; ++j) {
            int m = m0 + ty * 2 + i;
            int d = d0 + tx * 8 + j;
            float v = acc[i][j] + bias[d];
            float sp = (v > 20.f) ? v : log1pf(__expf(v));
            g_dt[(size_t)m * DI + d] = sp;
        }
}

// ---------------------------------------------------------------------------
// Selective scan + skip (u*D) + gate (silu(z)), fused.
// Block = 256 threads = 16 d-channels x 16 states; grid = B * DI/16 = 192.
// Warp layout: lanes 0-15 -> states of d(2w), lanes 16-31 -> states of d(2w+1).
// ---------------------------------------------------------------------------
#define SCAN_T 32
__global__ void __launch_bounds__(256) scan_kernel(
    const float* __restrict__ A_log, const float* __restrict__ Dvec)
{
    const int b  = blockIdx.x / (DI / 16);
    const int d0 = (blockIdx.x % (DI / 16)) * 16;
    const int tid  = threadIdx.x;
    const int lane = tid & 31;
    const int warp = tid >> 5;
    const int n    = lane & 15;
    const int dloc = (warp << 1) | (lane >> 4);
    const int d    = d0 + dloc;

    const float a = -__expf(A_log[d * NS + n]);

    __shared__ float dt_s[SCAN_T][16];
    __shared__ float u_s [SCAN_T][16];
    __shared__ float B_s [SCAN_T][16];
    __shared__ float C_s [SCAN_T][16];
    __shared__ float z_s [SCAN_T][16];
    __shared__ float yb  [SCAN_T][16];

    float h = 0.f;

    for (int l0 = 0; l0 < LL; l0 += SCAN_T) {
        for (int i = tid; i < SCAN_T * 16; i += 256) {
            int tt = i >> 4, dd = i & 15;
            size_t row = (size_t)(b * LL + l0 + tt);
            dt_s[tt][dd] = g_dt[row * DI + d0 + dd];
            u_s [tt][dd] = g_u [row * DI + d0 + dd];
            B_s [tt][dd] = g_xdbl[row * XP + RK + dd];
            C_s [tt][dd] = g_xdbl[row * XP + RK + NS + dd];
            z_s [tt][dd] = g_xz[row * (2 * DI) + DI + d0 + dd];
        }
        __syncthreads();

#pragma unroll 8
        for (int t = 0; t < SCAN_T; ++t) {
            float dtv = dt_s[t][dloc];
            float uv  = u_s [t][dloc];
            float Bv  = B_s [t][n];
            float Cv  = C_s [t][n];
            h = fmaf(h, __expf(dtv * a), dtv * uv * Bv);
            float p = h * Cv;
            p += __shfl_xor_sync(0xffffffffu, p, 8);
            p += __shfl_xor_sync(0xffffffffu, p, 4);
            p += __shfl_xor_sync(0xffffffffu, p, 2);
            p += __shfl_xor_sync(0xffffffffu, p, 1);
            if (n == 0) yb[t][dloc] = p;
        }
        __syncthreads();

        // epilogue: y = (y_scan + u*D) * silu(z)
        for (int i = tid; i < SCAN_T * 16; i += 256) {
            int tt = i >> 4, dd = i & 15;
            size_t row = (size_t)(b * LL + l0 + tt);
            float zz = z_s[tt][dd];
            float sz = zz / (1.f + __expf(-zz));
            float yv = fmaf(u_s[tt][dd], Dvec[d0 + dd], yb[tt][dd]) * sz;
            g_y[row * DI + d0 + dd] = yv;
        }
        __syncthreads();
    }
}

// ---------------------------------------------------------------------------
// residual + LayerNorm over DM=768; one block per row, 256 threads x 3 elems
// ---------------------------------------------------------------------------
__global__ void __launch_bounds__(256) resid_ln(
    const float* __restrict__ x, const float* __restrict__ w,
    const float* __restrict__ bln, float* __restrict__ out)
{
    const int row = blockIdx.x;
    const float* o  = g_ob + (size_t)row * DM;
    const float* xr = x    + (size_t)row * DM;

    float v[3];
    float s = 0.f, ss = 0.f;
#pragma unroll
    for (int i = 0; i < 3; ++i) {
        int c = threadIdx.x + i * 256;
        v[i] = o[c] + xr[c];
        s += v[i];
        ss += v[i] * v[i];
    }
#pragma unroll
    for (int off = 16; off; off >>= 1) {
        s  += __shfl_xor_sync(0xffffffffu, s,  off);
        ss += __shfl_xor_sync(0xffffffffu, ss, off);
    }
    __shared__ float sbuf[16];
    int warp = threadIdx.x >> 5, lane = threadIdx.x & 31;
    if (lane == 0) { sbuf[warp] = s; sbuf[8 + warp] = ss; }
    __syncthreads();
    float S = 0.f, SS = 0.f;
#pragma unroll
    for (int i = 0; i < 8; ++i) { S += sbuf[i]; SS += sbuf[8 + i]; }
    float mean = S * (1.f / DM);
    float var  = SS * (1.f / DM) - mean * mean;
    float rstd = rsqrtf(var + 1e-5f);
#pragma unroll
    for (int i = 0; i < 3; ++i) {
        int c = threadIdx.x + i * 256;
        out[(size_t)row * DM + c] = (v[i] - mean) * rstd * w[c] + bln[c];
    }
}

// ---------------------------------------------------------------------------
extern "C" void kernel_launch(void* const* d_in, const int* in_sizes, int n_in,
                              void* d_out, int out_size)
{
    const float* x       = (const float*)d_in[0];
    const float* in_w    = (const float*)d_in[1];
    const float* conv_w  = (const float*)d_in[2];
    const float* conv_b  = (const float*)d_in[3];
    const float* xproj_w = (const float*)d_in[4];
    const float* dt_w    = (const float*)d_in[5];
    const float* dt_b    = (const float*)d_in[6];
    const float* A_log   = (const float*)d_in[7];
    const float* Dv      = (const float*)d_in[8];
    const float* out_w   = (const float*)d_in[9];
    const float* ln_w    = (const float*)d_in[10];
    const float* ln_b    = (const float*)d_in[11];
    float* out = (float*)d_out;

    float *p_xz, *p_y, *p_ob;
    cudaGetSymbolAddress((void**)&p_xz, g_xz);
    cudaGetSymbolAddress((void**)&p_y,  g_y);
    cudaGetSymbolAddress((void**)&p_ob, g_ob);

    // 1) in_proj: xz = x @ in_proj_w^T   [4096, 3072]
    sgemm_nt<<<dim3((2 * DI) / 128, MROWS / 128), 256>>>(
        x, in_w, p_xz, MROWS, 2 * DI, DM);

    // 2) depthwise causal conv + silu -> g_u
    conv_silu_kernel<<<(MROWS * DI + 255) / 256, 256>>>(conv_w, conv_b);

    // 3) x_proj -> g_xdbl [4096, 80]
    gemm_xproj<<<MROWS / 32, 256>>>(xproj_w);

    // 4) dt_proj + softplus -> g_dt
    dtproj_softplus<<<dim3(MROWS / 32, DI / 128), 256>>>(dt_w, dt_b);

    // 5) selective scan + skip + gate -> g_y
    scan_kernel<<<BB * (DI / 16), 256>>>(A_log, Dv);

    // 6) out_proj: ob = y @ out_proj_w^T  [4096, 768]
    sgemm_nt<<<dim3(DM / 128, MROWS / 128), 256>>>(
        p_y, out_w, p_ob, MROWS, DM, DI);

    // 7) residual + LayerNorm -> out
    resid_ln<<<MROWS, 256>>>(x, ln_w, ln_b, out);
}

// round 6
// speedup vs baseline: 1.4401x; 1.4401x over previous
#include <cuda_runtime.h>
#include <cuda_bf16.h>
#include <math.h>
#include <stdint.h>

// ---------------------------------------------------------------------------
// MambaBlock: B=2, L=2048, D_MODEL=768, D_INNER=1536, D_STATE=16, DT_RANK=48
// ---------------------------------------------------------------------------
#define BB   2
#define LL   2048
#define DM   768
#define DI   1536
#define NS   16
#define RK   48
#define MROWS (BB * LL)       // 4096
#define XP    80              // DT_RANK + 2*D_STATE

// ---------------- scratch (device globals; no allocation allowed) ----------
__device__ float g_xz  [MROWS * 2 * DI];   // in_proj output [4096, 3072]
__device__ float g_u   [MROWS * DI];       // conv+silu output
__device__ float g_xdbl[MROWS * XP];       // x_proj output [4096, 80]
__device__ float g_dt  [MROWS * DI];       // softplus(dt_proj)
__device__ float g_y   [MROWS * DI];       // scan output, gated
__device__ float g_ob  [MROWS * DM];       // out_proj output

// ===========================================================================
// HMMA (mma.sync bf16) GEMM: C[M,N] = A[M,K] * B[N,K]^T, fp32 in/out.
// bf16 hi/lo split, 3 passes (Ah*Bh + Ah*Bl + Al*Bh), fp32 accum in regs.
// CTA tile 128x128, BK=32. 256 threads = 8 warps, warp tile 32x64.
// ===========================================================================
#define BM 128
#define BN 128
#define BK 32
#define SROW 40          // bf16 elements per smem row (80B stride: LDSM conflict-free)

__device__ __forceinline__ uint32_t smem_u32(const void* p) {
    uint32_t a;
    asm("{ .reg .u64 t; cvta.to.shared.u64 t, %1; cvt.u32.u64 %0, t; }"
        : "=r"(a) : "l"(p));
    return a;
}

__device__ __forceinline__ void ldsm_x4(uint32_t& r0, uint32_t& r1,
                                        uint32_t& r2, uint32_t& r3, uint32_t addr) {
    asm volatile("ldmatrix.sync.aligned.m8n8.x4.shared.b16 {%0,%1,%2,%3}, [%4];"
                 : "=r"(r0), "=r"(r1), "=r"(r2), "=r"(r3) : "r"(addr));
}
__device__ __forceinline__ void ldsm_x2(uint32_t& r0, uint32_t& r1, uint32_t addr) {
    asm volatile("ldmatrix.sync.aligned.m8n8.x2.shared.b16 {%0,%1}, [%2];"
                 : "=r"(r0), "=r"(r1) : "r"(addr));
}
__device__ __forceinline__ void mma_bf16(float* c, const uint32_t* a, const uint32_t* b) {
    asm volatile(
        "mma.sync.aligned.m16n8k16.row.col.f32.bf16.bf16.f32 "
        "{%0,%1,%2,%3}, {%4,%5,%6,%7}, {%8,%9}, {%0,%1,%2,%3};"
        : "+f"(c[0]), "+f"(c[1]), "+f"(c[2]), "+f"(c[3])
        : "r"(a[0]), "r"(a[1]), "r"(a[2]), "r"(a[3]), "r"(b[0]), "r"(b[1]));
}

// split one float4 into hi/lo bf16 quads (as 2x uint2)
__device__ __forceinline__ void split4(float4 v, uint2& hi, uint2& lo) {
    __nv_bfloat162 h01 = make_bfloat162(__float2bfloat16(v.x), __float2bfloat16(v.y));
    __nv_bfloat162 h23 = make_bfloat162(__float2bfloat16(v.z), __float2bfloat16(v.w));
    __nv_bfloat162 l01 = make_bfloat162(
        __float2bfloat16(v.x - __bfloat162float(h01.x)),
        __float2bfloat16(v.y - __bfloat162float(h01.y)));
    __nv_bfloat162 l23 = make_bfloat162(
        __float2bfloat16(v.z - __bfloat162float(h23.x)),
        __float2bfloat16(v.w - __bfloat162float(h23.y)));
    hi = make_uint2(*(uint32_t*)&h01, *(uint32_t*)&h23);
    lo = make_uint2(*(uint32_t*)&l01, *(uint32_t*)&l23);
}

__global__ void __launch_bounds__(256) gemm_hmma(
    const float* __restrict__ A, const float* __restrict__ B,
    float* __restrict__ C, int M, int N, int K)
{
    __shared__ __align__(16) __nv_bfloat16 sAh[BM * SROW];
    __shared__ __align__(16) __nv_bfloat16 sAl[BM * SROW];
    __shared__ __align__(16) __nv_bfloat16 sBh[BN * SROW];
    __shared__ __align__(16) __nv_bfloat16 sBl[BN * SROW];

    const int tid  = threadIdx.x;
    const int wid  = tid >> 5;
    const int lane = tid & 31;
    const int bm = blockIdx.y * BM;
    const int bn = blockIdx.x * BN;

    const int wm = (wid & 3) * 32;    // warp row offset within CTA tile
    const int wn = (wid >> 2) * 64;   // warp col offset within CTA tile

    const uint32_t uAh = smem_u32(sAh);
    const uint32_t uAl = smem_u32(sAl);
    const uint32_t uBh = smem_u32(sBh);
    const uint32_t uBl = smem_u32(sBl);

    float acc[2][8][4];
#pragma unroll
    for (int i = 0; i < 2; ++i)
#pragma unroll
        for (int j = 0; j < 8; ++j)
#pragma unroll
            for (int k = 0; k < 4; ++k) acc[i][j][k] = 0.f;

    // ldmatrix per-lane source addresses (element row within tile, k offset)
    // A x4: row = wm + mt*16 + (lane&15), k = ks*16 + (lane>>4)*8
    // B x2: row = wn + nt*8 + (lane&7),  k = ks*16 + ((lane>>3)&1)*8
    const int aRow = lane & 15;
    const int aKof = (lane >> 4) << 3;
    const int bRow = lane & 7;
    const int bKof = ((lane >> 3) & 1) << 3;

    for (int k0 = 0; k0 < K; k0 += BK) {
        // ---- load + split-convert A[128xBK], B[128xBK] into bf16 hi/lo ----
#pragma unroll
        for (int p = 0; p < 4; ++p) {
            int i = tid + p * 256;        // 0..1023 float4 slots
            int row = i >> 3;             // 0..127
            int kg  = i & 7;              // float4 group (4 floats)
            uint2 hi, lo;
            float4 va = *reinterpret_cast<const float4*>(
                A + (size_t)(bm + row) * K + k0 + kg * 4);
            split4(va, hi, lo);
            *reinterpret_cast<uint2*>(&sAh[row * SROW + kg * 4]) = hi;
            *reinterpret_cast<uint2*>(&sAl[row * SROW + kg * 4]) = lo;

            float4 vb = *reinterpret_cast<const float4*>(
                B + (size_t)(bn + row) * K + k0 + kg * 4);
            split4(vb, hi, lo);
            *reinterpret_cast<uint2*>(&sBh[row * SROW + kg * 4]) = hi;
            *reinterpret_cast<uint2*>(&sBl[row * SROW + kg * 4]) = lo;
        }
        __syncthreads();

        // ---- compute: 2 k-steps of m16n8k16, 3 passes ----
#pragma unroll
        for (int ks = 0; ks < 2; ++ks) {
            const int kb = ks * 16;
            uint32_t Ah[2][4], Al[2][4];
#pragma unroll
            for (int mt = 0; mt < 2; ++mt) {
                uint32_t off = (uint32_t)((wm + mt * 16 + aRow) * SROW + kb + aKof) * 2;
                ldsm_x4(Ah[mt][0], Ah[mt][1], Ah[mt][2], Ah[mt][3], uAh + off);
                ldsm_x4(Al[mt][0], Al[mt][1], Al[mt][2], Al[mt][3], uAl + off);
            }
#pragma unroll
            for (int nt = 0; nt < 8; ++nt) {
                uint32_t off = (uint32_t)((wn + nt * 8 + bRow) * SROW + kb + bKof) * 2;
                uint32_t Bh[2], Bl[2];
                ldsm_x2(Bh[0], Bh[1], uBh + off);
                ldsm_x2(Bl[0], Bl[1], uBl + off);
#pragma unroll
                for (int mt = 0; mt < 2; ++mt) {
                    mma_bf16(acc[mt][nt], Ah[mt], Bh);
                    mma_bf16(acc[mt][nt], Ah[mt], Bl);
                    mma_bf16(acc[mt][nt], Al[mt], Bh);
                }
            }
        }
        __syncthreads();
    }

    // ---- epilogue: direct register -> gmem stores (float2 per half-frag) ----
    const int g  = lane >> 2;
    const int cc = (lane & 3) * 2;
#pragma unroll
    for (int mt = 0; mt < 2; ++mt) {
#pragma unroll
        for (int nt = 0; nt < 8; ++nt) {
            int row0 = bm + wm + mt * 16 + g;
            int col  = bn + wn + nt * 8 + cc;
            *reinterpret_cast<float2*>(C + (size_t)row0 * N + col) =
                make_float2(acc[mt][nt][0], acc[mt][nt][1]);
            *reinterpret_cast<float2*>(C + (size_t)(row0 + 8) * N + col) =
                make_float2(acc[mt][nt][2], acc[mt][nt][3]);
        }
    }
}

// ---------------------------------------------------------------------------
// Depthwise causal conv (k=4) + bias + silu over u = xz[:, :, 0:DI]
// ---------------------------------------------------------------------------
__global__ void __launch_bounds__(256) conv_silu_kernel(
    const float* __restrict__ conv_w, const float* __restrict__ conv_b)
{
    int idx = blockIdx.x * blockDim.x + threadIdx.x;
    if (idx >= MROWS * DI) return;
    int d = idx % DI;
    int l = (idx / DI) % LL;
    int b = idx / (DI * LL);

    float acc = conv_b[d];
#pragma unroll
    for (int j = 0; j < 4; ++j) {
        int ll = l - 3 + j;
        if (ll >= 0)
            acc = fmaf(conv_w[d * 4 + j],
                       g_xz[(size_t)(b * LL + ll) * (2 * DI) + d], acc);
    }
    g_u[idx] = acc / (1.f + __expf(-acc));
}

// ---------------------------------------------------------------------------
// x_proj: x_dbl[4096,80] = u_act[4096,1536] * x_proj_w[80,1536]^T
// ---------------------------------------------------------------------------
__global__ void __launch_bounds__(256) gemm_xproj(
    const float* __restrict__ W)
{
    __shared__ float As[32][33];   // [k][m]
    __shared__ float Ws[32][81];   // [k][n]

    const int tid = threadIdx.x;
    const int m0 = blockIdx.x * 32;
    const int tx = tid & 15;       // n: 5 each
    const int ty = tid >> 4;       // m: 2 each

    float acc[2][5] = {};

    for (int k0 = 0; k0 < DI; k0 += 32) {
        for (int i = tid; i < 32 * 32; i += 256) {
            int m = i >> 5, k = i & 31;
            As[k][m] = g_u[(size_t)(m0 + m) * DI + k0 + k];
        }
        for (int i = tid; i < 80 * 32; i += 256) {
            int nn = i >> 5, k = i & 31;
            Ws[k][nn] = W[(size_t)nn * DI + k0 + k];
        }
        __syncthreads();
#pragma unroll
        for (int k = 0; k < 32; ++k) {
            float a0 = As[k][ty * 2];
            float a1 = As[k][ty * 2 + 1];
#pragma unroll
            for (int j = 0; j < 5; ++j) {
                float w = Ws[k][tx * 5 + j];
                acc[0][j] = fmaf(a0, w, acc[0][j]);
                acc[1][j] = fmaf(a1, w, acc[1][j]);
            }
        }
        __syncthreads();
    }
#pragma unroll
    for (int i = 0; i < 2; ++i)
#pragma unroll
        for (int j = 0; j < 5; ++j)
            g_xdbl[(size_t)(m0 + ty * 2 + i) * XP + tx * 5 + j] = acc[i][j];
}

// ---------------------------------------------------------------------------
// dt_proj (K=48) + bias + softplus
// ---------------------------------------------------------------------------
__global__ void __launch_bounds__(256) dtproj_softplus(
    const float* __restrict__ W, const float* __restrict__ bias)
{
    __shared__ float Ls[RK][33];
    __shared__ float Ws[RK][129];

    const int tid = threadIdx.x;
    const int m0 = blockIdx.x * 32;
    const int d0 = blockIdx.y * 128;

    for (int i = tid; i < 32 * RK; i += 256) {
        int m = i / RK, r = i % RK;
        Ls[r][m] = g_xdbl[(size_t)(m0 + m) * XP + r];
    }
    for (int i = tid; i < 128 * RK; i += 256) {
        int d = i / RK, r = i % RK;
        Ws[r][d] = W[(size_t)(d0 + d) * RK + r];
    }
    __syncthreads();

    const int tx = tid & 15;
    const int ty = tid >> 4;
    float acc[2][8] = {};
#pragma unroll
    for (int r = 0; r < RK; ++r) {
        float a0 = Ls[r][ty * 2];
        float a1 = Ls[r][ty * 2 + 1];
#pragma unroll
        for (int j = 0; j < 8; ++j) {
            float w = Ws[r][tx * 8 + j];
            acc[0][j] = fmaf(a0, w, acc[0][j]);
            acc[1][j] = fmaf(a1, w, acc[1][j]);
        }
    }
#pragma unroll
    for (int i = 0; i < 2; ++i)
#pragma unroll
        for (int j = 0; j < 8; ++j) {
            int m = m0 + ty * 2 + i;
            int d = d0 + tx * 8 + j;
            float v = acc[i][j] + bias[d];
            float sp = (v > 20.f) ? v : log1pf(__expf(v));
            g_dt[(size_t)m * DI + d] = sp;
        }
}

// ---------------------------------------------------------------------------
// Selective scan + skip (u*D) + gate (silu(z)), fused.
// ---------------------------------------------------------------------------
#define SCAN_T 32
__global__ void __launch_bounds__(256) scan_kernel(
    const float* __restrict__ A_log, const float* __restrict__ Dvec)
{
    const int b  = blockIdx.x / (DI / 16);
    const int d0 = (blockIdx.x % (DI / 16)) * 16;
    const int tid  = threadIdx.x;
    const int lane = tid & 31;
    const int warp = tid >> 5;
    const int n    = lane & 15;
    const int dloc = (warp << 1) | (lane >> 4);
    const int d    = d0 + dloc;

    const float a = -__expf(A_log[d * NS + n]);

    __shared__ float dt_s[SCAN_T][16];
    __shared__ float u_s [SCAN_T][16];
    __shared__ float B_s [SCAN_T][16];
    __shared__ float C_s [SCAN_T][16];
    __shared__ float z_s [SCAN_T][16];
    __shared__ float yb  [SCAN_T][16];

    float h = 0.f;

    for (int l0 = 0; l0 < LL; l0 += SCAN_T) {
        for (int i = tid; i < SCAN_T * 16; i += 256) {
            int tt = i >> 4, dd = i & 15;
            size_t row = (size_t)(b * LL + l0 + tt);
            dt_s[tt][dd] = g_dt[row * DI + d0 + dd];
            u_s [tt][dd] = g_u [row * DI + d0 + dd];
            B_s [tt][dd] = g_xdbl[row * XP + RK + dd];
            C_s [tt][dd] = g_xdbl[row * XP + RK + NS + dd];
            z_s [tt][dd] = g_xz[row * (2 * DI) + DI + d0 + dd];
        }
        __syncthreads();

#pragma unroll 8
        for (int t = 0; t < SCAN_T; ++t) {
            float dtv = dt_s[t][dloc];
            float uv  = u_s [t][dloc];
            float Bv  = B_s [t][n];
            float Cv  = C_s [t][n];
            h = fmaf(h, __expf(dtv * a), dtv * uv * Bv);
            float p = h * Cv;
            p += __shfl_xor_sync(0xffffffffu, p, 8);
            p += __shfl_xor_sync(0xffffffffu, p, 4);
            p += __shfl_xor_sync(0xffffffffu, p, 2);
            p += __shfl_xor_sync(0xffffffffu, p, 1);
            if (n == 0) yb[t][dloc] = p;
        }
        __syncthreads();

        for (int i = tid; i < SCAN_T * 16; i += 256) {
            int tt = i >> 4, dd = i & 15;
            size_t row = (size_t)(b * LL + l0 + tt);
            float zz = z_s[tt][dd];
            float sz = zz / (1.f + __expf(-zz));
            float yv = fmaf(u_s[tt][dd], Dvec[d0 + dd], yb[tt][dd]) * sz;
            g_y[row * DI + d0 + dd] = yv;
        }
        __syncthreads();
    }
}

// ---------------------------------------------------------------------------
// residual + LayerNorm over DM=768
// ---------------------------------------------------------------------------
__global__ void __launch_bounds__(256) resid_ln(
    const float* __restrict__ x, const float* __restrict__ w,
    const float* __restrict__ bln, float* __restrict__ out)
{
    const int row = blockIdx.x;
    const float* o  = g_ob + (size_t)row * DM;
    const float* xr = x    + (size_t)row * DM;

    float v[3];
    float s = 0.f, ss = 0.f;
#pragma unroll
    for (int i = 0; i < 3; ++i) {
        int c = threadIdx.x + i * 256;
        v[i] = o[c] + xr[c];
        s += v[i];
        ss += v[i] * v[i];
    }
#pragma unroll
    for (int off = 16; off; off >>= 1) {
        s  += __shfl_xor_sync(0xffffffffu, s,  off);
        ss += __shfl_xor_sync(0xffffffffu, ss, off);
    }
    __shared__ float sbuf[16];
    int warp = threadIdx.x >> 5, lane = threadIdx.x & 31;
    if (lane == 0) { sbuf[warp] = s; sbuf[8 + warp] = ss; }
    __syncthreads();
    float S = 0.f, SS = 0.f;
#pragma unroll
    for (int i = 0; i < 8; ++i) { S += sbuf[i]; SS += sbuf[8 + i]; }
    float mean = S * (1.f / DM);
    float var  = SS * (1.f / DM) - mean * mean;
    float rstd = rsqrtf(var + 1e-5f);
#pragma unroll
    for (int i = 0; i < 3; ++i) {
        int c = threadIdx.x + i * 256;
        out[(size_t)row * DM + c] = (v[i] - mean) * rstd * w[c] + bln[c];
    }
}

// ---------------------------------------------------------------------------
extern "C" void kernel_launch(void* const* d_in, const int* in_sizes, int n_in,
                              void* d_out, int out_size)
{
    const float* x       = (const float*)d_in[0];
    const float* in_w    = (const float*)d_in[1];
    const float* conv_w  = (const float*)d_in[2];
    const float* conv_b  = (const float*)d_in[3];
    const float* xproj_w = (const float*)d_in[4];
    const float* dt_w    = (const float*)d_in[5];
    const float* dt_b    = (const float*)d_in[6];
    const float* A_log   = (const float*)d_in[7];
    const float* Dv      = (const float*)d_in[8];
    const float* out_w   = (const float*)d_in[9];
    const float* ln_w    = (const float*)d_in[10];
    const float* ln_b    = (const float*)d_in[11];
    float* out = (float*)d_out;

    float *p_xz, *p_y, *p_ob;
    cudaGetSymbolAddress((void**)&p_xz, g_xz);
    cudaGetSymbolAddress((void**)&p_y,  g_y);
    cudaGetSymbolAddress((void**)&p_ob, g_ob);

    // 1) in_proj: xz = x @ in_proj_w^T   [4096, 3072]
    gemm_hmma<<<dim3((2 * DI) / BN, MROWS / BM), 256>>>(
        x, in_w, p_xz, MROWS, 2 * DI, DM);

    // 2) depthwise causal conv + silu -> g_u
    conv_silu_kernel<<<(MROWS * DI + 255) / 256, 256>>>(conv_w, conv_b);

    // 3) x_proj -> g_xdbl [4096, 80]
    gemm_xproj<<<MROWS / 32, 256>>>(xproj_w);

    // 4) dt_proj + softplus -> g_dt
    dtproj_softplus<<<dim3(MROWS / 32, DI / 128), 256>>>(dt_w, dt_b);

    // 5) selective scan + skip + gate -> g_y
    scan_kernel<<<BB * (DI / 16), 256>>>(A_log, Dv);

    // 6) out_proj: ob = y @ out_proj_w^T  [4096, 768]
    gemm_hmma<<<dim3(DM / BN, MROWS / BM), 256>>>(
        p_y, out_w, p_ob, MROWS, DM, DI);

    // 7) residual + LayerNorm -> out
    resid_ln<<<MROWS, 256>>>(x, ln_w, ln_b, out);
}

// round 8
// speedup vs baseline: 1.5447x; 1.0727x over previous
#include <cuda_runtime.h>
#include <cuda_bf16.h>
#include <math.h>
#include <stdint.h>

// ---------------------------------------------------------------------------
// MambaBlock: B=2, L=2048, D_MODEL=768, D_INNER=1536, D_STATE=16, DT_RANK=48
// ---------------------------------------------------------------------------
#define BB   2
#define LL   2048
#define DM   768
#define DI   1536
#define NS   16
#define RK   48
#define MROWS (BB * LL)       // 4096
#define XP    80              // DT_RANK + 2*D_STATE

// ---------------- scratch (device globals; no allocation allowed) ----------
__device__ float g_xz  [MROWS * 2 * DI];   // in_proj output [4096, 3072]
__device__ float g_u   [MROWS * DI];       // conv+silu output
__device__ float g_xdbl[MROWS * XP];       // x_proj output [4096, 80]
__device__ float g_dt  [MROWS * DI];       // softplus(dt_proj)
__device__ float g_y   [MROWS * DI];       // scan output, gated
__device__ float g_ob  [MROWS * DM];       // out_proj output
// bf16 hi/lo split staging
__device__ __nv_bfloat16 g_ah[MROWS * DI];     // A hi (max 4096x1536)
__device__ __nv_bfloat16 g_al[MROWS * DI];     // A lo
__device__ __nv_bfloat16 g_bh[2 * DI * DM];    // B hi (max 3072x768)
__device__ __nv_bfloat16 g_bl[2 * DI * DM];    // B lo

// ===========================================================================
// helpers
// ===========================================================================
__device__ __forceinline__ uint32_t smem_u32(const void* p) {
    uint32_t a;
    asm("{ .reg .u64 t; cvta.to.shared.u64 t, %1; cvt.u32.u64 %0, t; }"
        : "=r"(a) : "l"(p));
    return a;
}
__device__ __forceinline__ void ldsm_x4(uint32_t& r0, uint32_t& r1,
                                        uint32_t& r2, uint32_t& r3, uint32_t addr) {
    asm volatile("ldmatrix.sync.aligned.m8n8.x4.shared.b16 {%0,%1,%2,%3}, [%4];"
                 : "=r"(r0), "=r"(r1), "=r"(r2), "=r"(r3) : "r"(addr));
}
__device__ __forceinline__ void ldsm_x2(uint32_t& r0, uint32_t& r1, uint32_t addr) {
    asm volatile("ldmatrix.sync.aligned.m8n8.x2.shared.b16 {%0,%1}, [%2];"
                 : "=r"(r0), "=r"(r1) : "r"(addr));
}
__device__ __forceinline__ void mma_bf16(float* c, const uint32_t* a, const uint32_t* b) {
    asm volatile(
        "mma.sync.aligned.m16n8k16.row.col.f32.bf16.bf16.f32 "
        "{%0,%1,%2,%3}, {%4,%5,%6,%7}, {%8,%9}, {%0,%1,%2,%3};"
        : "+f"(c[0]), "+f"(c[1]), "+f"(c[2]), "+f"(c[3])
        : "r"(a[0]), "r"(a[1]), "r"(a[2]), "r"(a[3]), "r"(b[0]), "r"(b[1]));
}
#define CP_ASYNC16(dst, src) \
    asm volatile("cp.async.cg.shared.global [%0], [%1], 16;" :: "r"(dst), "l"(src))
#define CP_COMMIT() asm volatile("cp.async.commit_group;" ::: "memory")
#define CP_WAIT0()  asm volatile("cp.async.wait_group 0;" ::: "memory")

// split one float4 into hi/lo bf16 quads (as 2x uint2)
__device__ __forceinline__ void split4(float4 v, uint2& hi, uint2& lo) {
    __nv_bfloat162 h01 = make_bfloat162(__float2bfloat16(v.x), __float2bfloat16(v.y));
    __nv_bfloat162 h23 = make_bfloat162(__float2bfloat16(v.z), __float2bfloat16(v.w));
    __nv_bfloat162 l01 = make_bfloat162(
        __float2bfloat16(v.x - __bfloat162float(h01.x)),
        __float2bfloat16(v.y - __bfloat162float(h01.y)));
    __nv_bfloat162 l23 = make_bfloat162(
        __float2bfloat16(v.z - __bfloat162float(h23.x)),
        __float2bfloat16(v.w - __bfloat162float(h23.y)));
    hi = make_uint2(*(uint32_t*)&h01, *(uint32_t*)&h23);
    lo = make_uint2(*(uint32_t*)&l01, *(uint32_t*)&l23);
}

// fp32 -> (hi, lo) bf16 split, vectorized
__global__ void __launch_bounds__(256) split_kernel(
    const float4* __restrict__ src, uint2* __restrict__ hi,
    uint2* __restrict__ lo, int n4)
{
    int i = blockIdx.x * blockDim.x + threadIdx.x;
    if (i >= n4) return;
    uint2 h, l;
    split4(src[i], h, l);
    hi[i] = h; lo[i] = l;
}

// ===========================================================================
// bf16 HMMA GEMM, pre-split inputs, cp.async double-buffered.
// C[M,N] = (Ah+Al)[M,K] * (Bh+Bl)[N,K]^T (3 passes: AhBh + AhBl + AlBh)
// CTA tile 128x128, BK=32. 256 threads = 8 warps, warp tile 32x64.
// ===========================================================================
#define BM 128
#define BN 128
#define BK 32
#define SROW 40                          // bf16/row (80B: LDSM conflict-free)
#define TILE_B (BM * SROW * 2)           // 10240 bytes per tile
#define STAGE_B (4 * TILE_B)             // 40960 bytes per stage
#define GEMM_SMEM (2 * STAGE_B)          // 81920 bytes

__global__ void __launch_bounds__(256) gemm_bf16(
    const __nv_bfloat16* __restrict__ Ah, const __nv_bfloat16* __restrict__ Al,
    const __nv_bfloat16* __restrict__ Bh, const __nv_bfloat16* __restrict__ Bl,
    float* __restrict__ C, int M, int N, int K)
{
    extern __shared__ char smem[];
    const uint32_t sbase = smem_u32(smem);

    const int tid  = threadIdx.x;
    const int wid  = tid >> 5;
    const int lane = tid & 31;
    const int bm = blockIdx.y * BM;
    const int bn = blockIdx.x * BN;

    const int wm = (wid & 3) * 32;
    const int wn = (wid >> 2) * 64;

    float acc[2][8][4];
#pragma unroll
    for (int i = 0; i < 2; ++i)
#pragma unroll
        for (int j = 0; j < 8; ++j)
#pragma unroll
            for (int k = 0; k < 4; ++k) acc[i][j][k] = 0.f;

    const int aRow = lane & 15;
    const int aKof = (lane >> 4) << 3;
    const int bRow = lane & 7;
    const int bKof = ((lane >> 3) & 1) << 3;

    const __nv_bfloat16* srcs[4] = {Ah, Al, Bh, Bl};
    const int nch = K / BK;

    // ---- loader: 2048 x 16B chunks per stage, 8 per thread ----
    auto load_stage = [&](int stage, int k0) {
#pragma unroll
        for (int p = 0; p < 8; ++p) {
            int chunk = p * 256 + tid;
            int tile  = chunk >> 9;          // 0..3
            int idx   = chunk & 511;
            int row   = idx >> 2;            // 0..127
            int part  = idx & 3;             // 16B part within 64B row
            int grow  = (tile < 2 ? bm : bn) + row;
            const __nv_bfloat16* src = srcs[tile] + (size_t)grow * K + k0 + part * 8;
            uint32_t dst = sbase + stage * STAGE_B + tile * TILE_B
                         + row * (SROW * 2) + part * 16;
            CP_ASYNC16(dst, src);
        }
        CP_COMMIT();
    };

    load_stage(0, 0);

    for (int ch = 0; ch < nch; ++ch) {
        CP_WAIT0();
        __syncthreads();
        if (ch + 1 < nch) load_stage((ch + 1) & 1, (ch + 1) * BK);

        const uint32_t base = sbase + (ch & 1) * STAGE_B;
        const uint32_t uAh = base;
        const uint32_t uAl = base + TILE_B;
        const uint32_t uBh = base + 2 * TILE_B;
        const uint32_t uBl = base + 3 * TILE_B;

#pragma unroll
        for (int ks = 0; ks < 2; ++ks) {
            const int kb = ks * 16;
            uint32_t Afh[2][4], Afl[2][4];
#pragma unroll
            for (int mt = 0; mt < 2; ++mt) {
                uint32_t off = (uint32_t)((wm + mt * 16 + aRow) * SROW + kb + aKof) * 2;
                ldsm_x4(Afh[mt][0], Afh[mt][1], Afh[mt][2], Afh[mt][3], uAh + off);
                ldsm_x4(Afl[mt][0], Afl[mt][1], Afl[mt][2], Afl[mt][3], uAl + off);
            }
#pragma unroll
            for (int nt = 0; nt < 8; ++nt) {
                uint32_t off = (uint32_t)((wn + nt * 8 + bRow) * SROW + kb + bKof) * 2;
                uint32_t Bfh[2], Bfl[2];
                ldsm_x2(Bfh[0], Bfh[1], uBh + off);
                ldsm_x2(Bfl[0], Bfl[1], uBl + off);
#pragma unroll
                for (int mt = 0; mt < 2; ++mt) {
                    mma_bf16(acc[mt][nt], Afh[mt], Bfh);
                    mma_bf16(acc[mt][nt], Afh[mt], Bfl);
                    mma_bf16(acc[mt][nt], Afl[mt], Bfh);
                }
            }
        }
        __syncthreads();
    }

    // ---- epilogue: direct register -> gmem stores ----
    const int g  = lane >> 2;
    const int cc = (lane & 3) * 2;
#pragma unroll
    for (int mt = 0; mt < 2; ++mt) {
#pragma unroll
        for (int nt = 0; nt < 8; ++nt) {
            int row0 = bm + wm + mt * 16 + g;
            int col  = bn + wn + nt * 8 + cc;
            *reinterpret_cast<float2*>(C + (size_t)row0 * N + col) =
                make_float2(acc[mt][nt][0], acc[mt][nt][1]);
            *reinterpret_cast<float2*>(C + (size_t)(row0 + 8) * N + col) =
                make_float2(acc[mt][nt][2], acc[mt][nt][3]);
        }
    }
}

// ---------------------------------------------------------------------------
// Depthwise causal conv (k=4) + bias + silu over u = xz[:, :, 0:DI]
// ---------------------------------------------------------------------------
__global__ void __launch_bounds__(256) conv_silu_kernel(
    const float* __restrict__ conv_w, const float* __restrict__ conv_b)
{
    int idx = blockIdx.x * blockDim.x + threadIdx.x;
    if (idx >= MROWS * DI) return;
    int d = idx % DI;
    int l = (idx / DI) % LL;
    int b = idx / (DI * LL);

    float acc = conv_b[d];
#pragma unroll
    for (int j = 0; j < 4; ++j) {
        int ll = l - 3 + j;
        if (ll >= 0)
            acc = fmaf(conv_w[d * 4 + j],
                       g_xz[(size_t)(b * LL + ll) * (2 * DI) + d], acc);
    }
    g_u[idx] = acc / (1.f + __expf(-acc));
}

// ---------------------------------------------------------------------------
// x_proj: x_dbl[4096,80] = u_act[4096,1536] * x_proj_w[80,1536]^T
// ---------------------------------------------------------------------------
__global__ void __launch_bounds__(256) gemm_xproj(
    const float* __restrict__ W)
{
    __shared__ float As[32][33];   // [k][m]
    __shared__ float Ws[32][81];   // [k][n]

    const int tid = threadIdx.x;
    const int m0 = blockIdx.x * 32;
    const int tx = tid & 15;       // n: 5 each
    const int ty = tid >> 4;       // m: 2 each

    float acc[2][5] = {};

    for (int k0 = 0; k0 < DI; k0 += 32) {
        for (int i = tid; i < 32 * 32; i += 256) {
            int m = i >> 5, k = i & 31;
            As[k][m] = g_u[(size_t)(m0 + m) * DI + k0 + k];
        }
        for (int i = tid; i < 80 * 32; i += 256) {
            int nn = i >> 5, k = i & 31;
            Ws[k][nn] = W[(size_t)nn * DI + k0 + k];
        }
        __syncthreads();
#pragma unroll
        for (int k = 0; k < 32; ++k) {
            float a0 = As[k][ty * 2];
            float a1 = As[k][ty * 2 + 1];
#pragma unroll
            for (int j = 0; j < 5; ++j) {
                float w = Ws[k][tx * 5 + j];
                acc[0][j] = fmaf(a0, w, acc[0][j]);
                acc[1][j] = fmaf(a1, w, acc[1][j]);
            }
        }
        __syncthreads();
    }
#pragma unroll
    for (int i = 0; i < 2; ++i)
#pragma unroll
        for (int j = 0; j < 5; ++j)
            g_xdbl[(size_t)(m0 + ty * 2 + i) * XP + tx * 5 + j] = acc[i][j];
}

// ---------------------------------------------------------------------------
// dt_proj (K=48) + bias + softplus (fast __logf/__expf)
// ---------------------------------------------------------------------------
__global__ void __launch_bounds__(256) dtproj_softplus(
    const float* __restrict__ W, const float* __restrict__ bias)
{
    __shared__ float Ls[RK][33];
    __shared__ float Ws[RK][129];

    const int tid = threadIdx.x;
    const int m0 = blockIdx.x * 32;
    const int d0 = blockIdx.y * 128;

    for (int i = tid; i < 32 * RK; i += 256) {
        int m = i / RK, r = i % RK;
        Ls[r][m] = g_xdbl[(size_t)(m0 + m) * XP + r];
    }
    for (int i = tid; i < 128 * RK; i += 256) {
        int d = i / RK, r = i % RK;
        Ws[r][d] = W[(size_t)(d0 + d) * RK + r];
    }
    __syncthreads();

    const int tx = tid & 15;
    const int ty = tid >> 4;
    float acc[2][8] = {};
#pragma unroll
    for (int r = 0; r < RK; ++r) {
        float a0 = Ls[r][ty * 2];
        float a1 = Ls[r][ty * 2 + 1];
#pragma unroll
        for (int j = 0; j < 8; ++j) {
            float w = Ws[r][tx * 8 + j];
            acc[0][j] = fmaf(a0, w, acc[0][j]);
            acc[1][j] = fmaf(a1, w, acc[1][j]);
        }
    }
#pragma unroll
    for (int i = 0; i < 2; ++i)
#pragma unroll
        for (int j = 0; j < 8; ++j) {
            int m = m0 + ty * 2 + i;
            int d = d0 + tx * 8 + j;
            float v = acc[i][j] + bias[d];
            float sp = (v > 20.f) ? v : __logf(1.f + __expf(v));
            g_dt[(size_t)m * DI + d] = sp;
        }
}

// ---------------------------------------------------------------------------
// Selective scan + skip (u*D) + gate (silu(z)), fused.
// ---------------------------------------------------------------------------
#define SCAN_T 32
__global__ void __launch_bounds__(256) scan_kernel(
    const float* __restrict__ A_log, const float* __restrict__ Dvec)
{
    const int b  = blockIdx.x / (DI / 16);
    const int d0 = (blockIdx.x % (DI / 16)) * 16;
    const int tid  = threadIdx.x;
    const int lane = tid & 31;
    const int warp = tid >> 5;
    const int n    = lane & 15;
    const int dloc = (warp << 1) | (lane >> 4);
    const int d    = d0 + dloc;

    const float a = -__expf(A_log[d * NS + n]);

    __shared__ float dt_s[SCAN_T][16];
    __shared__ float u_s [SCAN_T][16];
    __shared__ float B_s [SCAN_T][16];
    __shared__ float C_s [SCAN_T][16];
    __shared__ float z_s [SCAN_T][16];
    __shared__ float yb  [SCAN_T][16];

    float h = 0.f;

    for (int l0 = 0; l0 < LL; l0 += SCAN_T) {
        for (int i = tid; i < SCAN_T * 16; i += 256) {
            int tt = i >> 4, dd = i & 15;
            size_t row = (size_t)(b * LL + l0 + tt);
            dt_s[tt][dd] = g_dt[row * DI + d0 + dd];
            u_s [tt][dd] = g_u [row * DI + d0 + dd];
            B_s [tt][dd] = g_xdbl[row * XP + RK + dd];
            C_s [tt][dd] = g_xdbl[row * XP + RK + NS + dd];
            z_s [tt][dd] = g_xz[row * (2 * DI) + DI + d0 + dd];
        }
        __syncthreads();

#pragma unroll 8
        for (int t = 0; t < SCAN_T; ++t) {
            float dtv = dt_s[t][dloc];
            float uv  = u_s [t][dloc];
            float Bv  = B_s [t][n];
            float Cv  = C_s [t][n];
            h = fmaf(h, __expf(dtv * a), dtv * uv * Bv);
            float p = h * Cv;
            p += __shfl_xor_sync(0xffffffffu, p, 8);
            p += __shfl_xor_sync(0xffffffffu, p, 4);
            p += __shfl_xor_sync(0xffffffffu, p, 2);
            p += __shfl_xor_sync(0xffffffffu, p, 1);
            if (n == 0) yb[t][dloc] = p;
        }
        __syncthreads();

        for (int i = tid; i < SCAN_T * 16; i += 256) {
            int tt = i >> 4, dd = i & 15;
            size_t row = (size_t)(b * LL + l0 + tt);
            float zz = z_s[tt][dd];
            float sz = zz / (1.f + __expf(-zz));
            float yv = fmaf(u_s[tt][dd], Dvec[d0 + dd], yb[tt][dd]) * sz;
            g_y[row * DI + d0 + dd] = yv;
        }
        __syncthreads();
    }
}

// ---------------------------------------------------------------------------
// residual + LayerNorm over DM=768
// ---------------------------------------------------------------------------
__global__ void __launch_bounds__(256) resid_ln(
    const float* __restrict__ x, const float* __restrict__ w,
    const float* __restrict__ bln, float* __restrict__ out)
{
    const int row = blockIdx.x;
    const float* o  = g_ob + (size_t)row * DM;
    const float* xr = x    + (size_t)row * DM;

    float v[3];
    float s = 0.f, ss = 0.f;
#pragma unroll
    for (int i = 0; i < 3; ++i) {
        int c = threadIdx.x + i * 256;
        v[i] = o[c] + xr[c];
        s += v[i];
        ss += v[i] * v[i];
    }
#pragma unroll
    for (int off = 16; off; off >>= 1) {
        s  += __shfl_xor_sync(0xffffffffu, s,  off);
        ss += __shfl_xor_sync(0xffffffffu, ss, off);
    }
    __shared__ float sbuf[16];
    int warp = threadIdx.x >> 5, lane = threadIdx.x & 31;
    if (lane == 0) { sbuf[warp] = s; sbuf[8 + warp] = ss; }
    __syncthreads();
    float S = 0.f, SS = 0.f;
#pragma unroll
    for (int i = 0; i < 8; ++i) { S += sbuf[i]; SS += sbuf[8 + i]; }
    float mean = S * (1.f / DM);
    float var  = SS * (1.f / DM) - mean * mean;
    float rstd = rsqrtf(var + 1e-5f);
#pragma unroll
    for (int i = 0; i < 3; ++i) {
        int c = threadIdx.x + i * 256;
        out[(size_t)row * DM + c] = (v[i] - mean) * rstd * w[c] + bln[c];
    }
}

// ---------------------------------------------------------------------------
extern "C" void kernel_launch(void* const* d_in, const int* in_sizes, int n_in,
                              void* d_out, int out_size)
{
    const float* x       = (const float*)d_in[0];
    const float* in_w    = (const float*)d_in[1];
    const float* conv_w  = (const float*)d_in[2];
    const float* conv_b  = (const float*)d_in[3];
    const float* xproj_w = (const float*)d_in[4];
    const float* dt_w    = (const float*)d_in[5];
    const float* dt_b    = (const float*)d_in[6];
    const float* A_log   = (const float*)d_in[7];
    const float* Dv      = (const float*)d_in[8];
    const float* out_w   = (const float*)d_in[9];
    const float* ln_w    = (const float*)d_in[10];
    const float* ln_b    = (const float*)d_in[11];
    float* out = (float*)d_out;

    float *p_xz, *p_y, *p_ob;
    cudaGetSymbolAddress((void**)&p_xz, g_xz);
    cudaGetSymbolAddress((void**)&p_y,  g_y);
    cudaGetSymbolAddress((void**)&p_ob, g_ob);
    __nv_bfloat16 *p_ah, *p_al, *p_bh, *p_bl;
    cudaGetSymbolAddress((void**)&p_ah, g_ah);
    cudaGetSymbolAddress((void**)&p_al, g_al);
    cudaGetSymbolAddress((void**)&p_bh, g_bh);
    cudaGetSymbolAddress((void**)&p_bl, g_bl);

    cudaFuncSetAttribute(gemm_bf16, cudaFuncAttributeMaxDynamicSharedMemorySize,
                         GEMM_SMEM);

    // 0a) split x -> A hi/lo
    {
        int n4 = MROWS * DM / 4;
        split_kernel<<<(n4 + 255) / 256, 256>>>(
            (const float4*)x, (uint2*)p_ah, (uint2*)p_al, n4);
    }
    // 0b) split in_proj_w -> B hi/lo
    {
        int n4 = 2 * DI * DM / 4;
        split_kernel<<<(n4 + 255) / 256, 256>>>(
            (const float4*)in_w, (uint2*)p_bh, (uint2*)p_bl, n4);
    }

    // 1) in_proj: xz = x @ in_proj_w^T   [4096, 3072]
    gemm_bf16<<<dim3((2 * DI) / BN, MROWS / BM), 256, GEMM_SMEM>>>(
        p_ah, p_al, p_bh, p_bl, p_xz, MROWS, 2 * DI, DM);

    // 2) depthwise causal conv + silu -> g_u
    conv_silu_kernel<<<(MROWS * DI + 255) / 256, 256>>>(conv_w, conv_b);

    // 3) x_proj -> g_xdbl [4096, 80]
    gemm_xproj<<<MROWS / 32, 256>>>(xproj_w);

    // 4) dt_proj + softplus -> g_dt
    dtproj_softplus<<<dim3(MROWS / 32, DI / 128), 256>>>(dt_w, dt_b);

    // 5) selective scan + skip + gate -> g_y
    scan_kernel<<<BB * (DI / 16), 256>>>(A_log, Dv);

    // 6a) split y -> A hi/lo
    {
        int n4 = MROWS * DI / 4;
        split_kernel<<<(n4 + 255) / 256, 256>>>(
            (const float4*)p_y, (uint2*)p_ah, (uint2*)p_al, n4);
    }
    // 6b) split out_proj_w -> B hi/lo
    {
        int n4 = DM * DI / 4;
        split_kernel<<<(n4 + 255) / 256, 256>>>(
            (const float4*)out_w, (uint2*)p_bh, (uint2*)p_bl, n4);
    }

    // 6c) out_proj: ob = y @ out_proj_w^T  [4096, 768]
    gemm_bf16<<<dim3(DM / BN, MROWS / BM), 256, GEMM_SMEM>>>(
        p_ah, p_al, p_bh, p_bl, p_ob, MROWS, DM, DI);

    // 7) residual + LayerNorm -> out
    resid_ln<<<MROWS, 256>>>(x, ln_w, ln_b, out);
}

// round 9
// speedup vs baseline: 1.5913x; 1.0301x over previous
#include <cuda_runtime.h>
#include <cuda_fp16.h>
#include <math.h>
#include <stdint.h>

// ---------------------------------------------------------------------------
// MambaBlock: B=2, L=2048, D_MODEL=768, D_INNER=1536, D_STATE=16, DT_RANK=48
// ---------------------------------------------------------------------------
#define BB   2
#define LL   2048
#define DM   768
#define DI   1536
#define NS   16
#define RK   48
#define MROWS (BB * LL)       // 4096
#define XP    80              // DT_RANK + 2*D_STATE

// ---------------- scratch (device globals; no allocation allowed) ----------
__device__ float g_xz  [MROWS * 2 * DI];   // in_proj output [4096, 3072]
__device__ float g_u   [MROWS * DI];       // conv+silu output
__device__ float g_xdbl[MROWS * XP];       // x_proj output [4096, 80]
__device__ float g_dt  [MROWS * DI];       // softplus(dt_proj)
__device__ float g_ob  [MROWS * DM];       // out_proj output
// fp16 staging for tensor GEMMs
__device__ __half g_ah[MROWS * DI];        // A hi  (max 4096x1536)
__device__ __half g_al[MROWS * DI];        // A lo
__device__ __half g_bh[2 * DI * DM];       // B hi  (max 3072x768)

// ===========================================================================
// helpers
// ===========================================================================
__device__ __forceinline__ uint32_t smem_u32(const void* p) {
    uint32_t a;
    asm("{ .reg .u64 t; cvta.to.shared.u64 t, %1; cvt.u32.u64 %0, t; }"
        : "=r"(a) : "l"(p));
    return a;
}
__device__ __forceinline__ void ldsm_x4(uint32_t& r0, uint32_t& r1,
                                        uint32_t& r2, uint32_t& r3, uint32_t addr) {
    asm volatile("ldmatrix.sync.aligned.m8n8.x4.shared.b16 {%0,%1,%2,%3}, [%4];"
                 : "=r"(r0), "=r"(r1), "=r"(r2), "=r"(r3) : "r"(addr));
}
__device__ __forceinline__ void mma_f16(float* c, const uint32_t* a,
                                        uint32_t b0, uint32_t b1) {
    asm volatile(
        "mma.sync.aligned.m16n8k16.row.col.f32.f16.f16.f32 "
        "{%0,%1,%2,%3}, {%4,%5,%6,%7}, {%8,%9}, {%0,%1,%2,%3};"
        : "+f"(c[0]), "+f"(c[1]), "+f"(c[2]), "+f"(c[3])
        : "r"(a[0]), "r"(a[1]), "r"(a[2]), "r"(a[3]), "r"(b0), "r"(b1));
}
#define CP_ASYNC16(dst, src) \
    asm volatile("cp.async.cg.shared.global [%0], [%1], 16;" :: "r"(dst), "l"(src))
#define CP_COMMIT() asm volatile("cp.async.commit_group;" ::: "memory")
#define CP_WAIT0()  asm volatile("cp.async.wait_group 0;" ::: "memory")

// fp16 hi/lo split of a float4 (hi = rn(x), lo = rn(x - hi))
__device__ __forceinline__ void split4h(float4 v, uint2& hi, uint2& lo) {
    __half hx = __float2half(v.x), hy = __float2half(v.y);
    __half hz = __float2half(v.z), hw = __float2half(v.w);
    __half lx = __float2half(v.x - __half2float(hx));
    __half ly = __float2half(v.y - __half2float(hy));
    __half lz = __float2half(v.z - __half2float(hz));
    __half lw = __float2half(v.w - __half2float(hw));
    __half2 h01 = __halves2half2(hx, hy), h23 = __halves2half2(hz, hw);
    __half2 l01 = __halves2half2(lx, ly), l23 = __halves2half2(lz, lw);
    hi = make_uint2(*(uint32_t*)&h01, *(uint32_t*)&h23);
    lo = make_uint2(*(uint32_t*)&l01, *(uint32_t*)&l23);
}

// fp32 -> fp16 hi/lo split
__global__ void __launch_bounds__(256) split_kernel(
    const float4* __restrict__ src, uint2* __restrict__ hi,
    uint2* __restrict__ lo, int n4)
{
    int i = blockIdx.x * blockDim.x + threadIdx.x;
    if (i >= n4) return;
    uint2 h, l;
    split4h(src[i], h, l);
    hi[i] = h; lo[i] = l;
}
// fp32 -> fp16 (single rounding; for weights)
__global__ void __launch_bounds__(256) convert_kernel(
    const float4* __restrict__ src, uint2* __restrict__ hi, int n4)
{
    int i = blockIdx.x * blockDim.x + threadIdx.x;
    if (i >= n4) return;
    float4 v = src[i];
    __half2 h01 = __halves2half2(__float2half(v.x), __float2half(v.y));
    __half2 h23 = __halves2half2(__float2half(v.z), __float2half(v.w));
    hi[i] = make_uint2(*(uint32_t*)&h01, *(uint32_t*)&h23);
}

// ===========================================================================
// fp16 HMMA GEMM, 2-pass: C[M,N] = (Ah+Al)[M,K] * Bh[N,K]^T, fp32 accum.
// CTA tile 128x128, BK=32, cp.async double-buffered.
// 256 threads = 8 warps, warp tile 32x64.
// ===========================================================================
#define BM 128
#define BN 128
#define BK 32
#define SROW 40                          // fp16/row (80B: LDSM conflict-free)
#define TILE_B (BM * SROW * 2)           // 10240 bytes per tile
#define STAGE_B (3 * TILE_B)             // 30720 bytes per stage (Ah, Al, Bh)
#define GEMM_SMEM (2 * STAGE_B)          // 61440 bytes

__global__ void __launch_bounds__(256) gemm_f16(
    const __half* __restrict__ Ah, const __half* __restrict__ Al,
    const __half* __restrict__ Bh,
    float* __restrict__ C, int M, int N, int K)
{
    extern __shared__ char smem[];
    const uint32_t sbase = smem_u32(smem);

    const int tid  = threadIdx.x;
    const int wid  = tid >> 5;
    const int lane = tid & 31;
    const int bm = blockIdx.y * BM;
    const int bn = blockIdx.x * BN;

    const int wm = (wid & 3) * 32;
    const int wn = (wid >> 2) * 64;

    float acc[2][8][4];
#pragma unroll
    for (int i = 0; i < 2; ++i)
#pragma unroll
        for (int j = 0; j < 8; ++j)
#pragma unroll
            for (int k = 0; k < 4; ++k) acc[i][j][k] = 0.f;

    // ldmatrix lane address components
    const int aRow = lane & 15;           // A: 16 rows
    const int aKof = (lane >> 4) << 3;    //    2 k-halves
    const int bRow = lane & 15;           // B x4: 16 rows (2 n-tiles)
    const int bKof = (lane >> 4) << 3;    //    2 k-halves

    const __half* srcs[3] = {Ah, Al, Bh};
    const int nch = K / BK;

    // ---- loader: 1536 x 16B chunks per stage, 6 per thread ----
    auto load_stage = [&](int stage, int k0) {
#pragma unroll
        for (int p = 0; p < 6; ++p) {
            int chunk = p * 256 + tid;
            int tile  = chunk >> 9;          // 0..2
            int idx   = chunk & 511;
            int row   = idx >> 2;            // 0..127
            int part  = idx & 3;             // 16B part within 64B row
            int grow  = (tile < 2 ? bm : bn) + row;
            const __half* src = srcs[tile] + (size_t)grow * K + k0 + part * 8;
            uint32_t dst = sbase + stage * STAGE_B + tile * TILE_B
                         + row * (SROW * 2) + part * 16;
            CP_ASYNC16(dst, src);
        }
        CP_COMMIT();
    };

    load_stage(0, 0);

    for (int ch = 0; ch < nch; ++ch) {
        CP_WAIT0();
        __syncthreads();
        if (ch + 1 < nch) load_stage((ch + 1) & 1, (ch + 1) * BK);

        const uint32_t base = sbase + (ch & 1) * STAGE_B;
        const uint32_t uAh = base;
        const uint32_t uAl = base + TILE_B;
        const uint32_t uBh = base + 2 * TILE_B;

#pragma unroll
        for (int ks = 0; ks < 2; ++ks) {
            const int kb = ks * 16;
            uint32_t Afh[2][4], Afl[2][4];
#pragma unroll
            for (int mt = 0; mt < 2; ++mt) {
                uint32_t off = (uint32_t)((wm + mt * 16 + aRow) * SROW + kb + aKof) * 2;
                ldsm_x4(Afh[mt][0], Afh[mt][1], Afh[mt][2], Afh[mt][3], uAh + off);
                ldsm_x4(Afl[mt][0], Afl[mt][1], Afl[mt][2], Afl[mt][3], uAl + off);
            }
#pragma unroll
            for (int nt2 = 0; nt2 < 4; ++nt2) {
                // x4 covers 16 B-rows = two n-tiles: even={r0,r2}, odd={r1,r3}
                uint32_t b0, b1, b2, b3;
                uint32_t off = (uint32_t)((wn + nt2 * 16 + bRow) * SROW + kb + bKof) * 2;
                ldsm_x4(b0, b1, b2, b3, uBh + off);
#pragma unroll
                for (int mt = 0; mt < 2; ++mt) {
                    mma_f16(acc[mt][nt2 * 2],     Afh[mt], b0, b2);
                    mma_f16(acc[mt][nt2 * 2],     Afl[mt], b0, b2);
                    mma_f16(acc[mt][nt2 * 2 + 1], Afh[mt], b1, b3);
                    mma_f16(acc[mt][nt2 * 2 + 1], Afl[mt], b1, b3);
                }
            }
        }
        __syncthreads();
    }

    // ---- epilogue: direct register -> gmem stores ----
    const int g  = lane >> 2;
    const int cc = (lane & 3) * 2;
#pragma unroll
    for (int mt = 0; mt < 2; ++mt) {
#pragma unroll
        for (int nt = 0; nt < 8; ++nt) {
            int row0 = bm + wm + mt * 16 + g;
            int col  = bn + wn + nt * 8 + cc;
            *reinterpret_cast<float2*>(C + (size_t)row0 * N + col) =
                make_float2(acc[mt][nt][0], acc[mt][nt][1]);
            *reinterpret_cast<float2*>(C + (size_t)(row0 + 8) * N + col) =
                make_float2(acc[mt][nt][2], acc[mt][nt][3]);
        }
    }
}

// ---------------------------------------------------------------------------
// Depthwise causal conv (k=4) + bias + silu over u = xz[:, :, 0:DI]
// ---------------------------------------------------------------------------
__global__ void __launch_bounds__(256) conv_silu_kernel(
    const float* __restrict__ conv_w, const float* __restrict__ conv_b)
{
    int idx = blockIdx.x * blockDim.x + threadIdx.x;
    if (idx >= MROWS * DI) return;
    int d = idx % DI;
    int l = (idx / DI) % LL;
    int b = idx / (DI * LL);

    float acc = conv_b[d];
#pragma unroll
    for (int j = 0; j < 4; ++j) {
        int ll = l - 3 + j;
        if (ll >= 0)
            acc = fmaf(conv_w[d * 4 + j],
                       g_xz[(size_t)(b * LL + ll) * (2 * DI) + d], acc);
    }
    g_u[idx] = acc / (1.f + __expf(-acc));
}

// ---------------------------------------------------------------------------
// x_proj: x_dbl[4096,80] = u_act[4096,1536] * x_proj_w[80,1536]^T
// ---------------------------------------------------------------------------
__global__ void __launch_bounds__(256) gemm_xproj(
    const float* __restrict__ W)
{
    __shared__ float As[32][33];   // [k][m]
    __shared__ float Ws[32][81];   // [k][n]

    const int tid = threadIdx.x;
    const int m0 = blockIdx.x * 32;
    const int tx = tid & 15;       // n: 5 each
    const int ty = tid >> 4;       // m: 2 each

    float acc[2][5] = {};

    for (int k0 = 0; k0 < DI; k0 += 32) {
        for (int i = tid; i < 32 * 32; i += 256) {
            int m = i >> 5, k = i & 31;
            As[k][m] = g_u[(size_t)(m0 + m) * DI + k0 + k];
        }
        for (int i = tid; i < 80 * 32; i += 256) {
            int nn = i >> 5, k = i & 31;
            Ws[k][nn] = W[(size_t)nn * DI + k0 + k];
        }
        __syncthreads();
#pragma unroll
        for (int k = 0; k < 32; ++k) {
            float a0 = As[k][ty * 2];
            float a1 = As[k][ty * 2 + 1];
#pragma unroll
            for (int j = 0; j < 5; ++j) {
                float w = Ws[k][tx * 5 + j];
                acc[0][j] = fmaf(a0, w, acc[0][j]);
                acc[1][j] = fmaf(a1, w, acc[1][j]);
            }
        }
        __syncthreads();
    }
#pragma unroll
    for (int i = 0; i < 2; ++i)
#pragma unroll
        for (int j = 0; j < 5; ++j)
            g_xdbl[(size_t)(m0 + ty * 2 + i) * XP + tx * 5 + j] = acc[i][j];
}

// ---------------------------------------------------------------------------
// dt_proj (K=48) + bias + softplus (fast __logf/__expf)
// ---------------------------------------------------------------------------
__global__ void __launch_bounds__(256) dtproj_softplus(
    const float* __restrict__ W, const float* __restrict__ bias)
{
    __shared__ float Ls[RK][33];
    __shared__ float Ws[RK][129];

    const int tid = threadIdx.x;
    const int m0 = blockIdx.x * 32;
    const int d0 = blockIdx.y * 128;

    for (int i = tid; i < 32 * RK; i += 256) {
        int m = i / RK, r = i % RK;
        Ls[r][m] = g_xdbl[(size_t)(m0 + m) * XP + r];
    }
    for (int i = tid; i < 128 * RK; i += 256) {
        int d = i / RK, r = i % RK;
        Ws[r][d] = W[(size_t)(d0 + d) * RK + r];
    }
    __syncthreads();

    const int tx = tid & 15;
    const int ty = tid >> 4;
    float acc[2][8] = {};
#pragma unroll
    for (int r = 0; r < RK; ++r) {
        float a0 = Ls[r][ty * 2];
        float a1 = Ls[r][ty * 2 + 1];
#pragma unroll
        for (int j = 0; j < 8; ++j) {
            float w = Ws[r][tx * 8 + j];
            acc[0][j] = fmaf(a0, w, acc[0][j]);
            acc[1][j] = fmaf(a1, w, acc[1][j]);
        }
    }
#pragma unroll
    for (int i = 0; i < 2; ++i)
#pragma unroll
        for (int j = 0; j < 8; ++j) {
            int m = m0 + ty * 2 + i;
            int d = d0 + tx * 8 + j;
            float v = acc[i][j] + bias[d];
            float sp = (v > 20.f) ? v : __logf(1.f + __expf(v));
            g_dt[(size_t)m * DI + d] = sp;
        }
}

// ---------------------------------------------------------------------------
// Selective scan + skip (u*D) + gate (silu(z)), fused; writes y as fp16 hi/lo
// directly into the GEMM A staging buffers.
// Block = 128 threads = 8 d-channels x 16 states; grid = B * DI/8 = 384.
// ---------------------------------------------------------------------------
#define SCAN_T 32
#define SCAN_D 8
__global__ void __launch_bounds__(128) scan_kernel(
    const float* __restrict__ A_log, const float* __restrict__ Dvec)
{
    const int b  = blockIdx.x / (DI / SCAN_D);
    const int d0 = (blockIdx.x % (DI / SCAN_D)) * SCAN_D;
    const int tid  = threadIdx.x;
    const int lane = tid & 31;
    const int warp = tid >> 5;                 // 0..3
    const int n    = lane & 15;
    const int dloc = (warp << 1) | (lane >> 4); // 0..7
    const int d    = d0 + dloc;

    const float a = -__expf(A_log[d * NS + n]);

    __shared__ float dt_s[SCAN_T][SCAN_D];
    __shared__ float u_s [SCAN_T][SCAN_D];
    __shared__ float z_s [SCAN_T][SCAN_D];
    __shared__ float B_s [SCAN_T][16];
    __shared__ float C_s [SCAN_T][16];
    __shared__ float yb  [SCAN_T][SCAN_D];

    float h = 0.f;

    for (int l0 = 0; l0 < LL; l0 += SCAN_T) {
        // d-indexed arrays: 256 items, 2/thread
        for (int i = tid; i < SCAN_T * SCAN_D; i += 128) {
            int tt = i >> 3, dd = i & 7;
            size_t row = (size_t)(b * LL + l0 + tt);
            dt_s[tt][dd] = g_dt[row * DI + d0 + dd];
            u_s [tt][dd] = g_u [row * DI + d0 + dd];
            z_s [tt][dd] = g_xz[row * (2 * DI) + DI + d0 + dd];
        }
        // n-indexed arrays: 512 items, 4/thread
        for (int i = tid; i < SCAN_T * 16; i += 128) {
            int tt = i >> 4, nn = i & 15;
            size_t row = (size_t)(b * LL + l0 + tt);
            B_s[tt][nn] = g_xdbl[row * XP + RK + nn];
            C_s[tt][nn] = g_xdbl[row * XP + RK + NS + nn];
        }
        __syncthreads();

#pragma unroll 8
        for (int t = 0; t < SCAN_T; ++t) {
            float dtv = dt_s[t][dloc];
            float uv  = u_s [t][dloc];
            float Bv  = B_s [t][n];
            float Cv  = C_s [t][n];
            h = fmaf(h, __expf(dtv * a), dtv * uv * Bv);
            float p = h * Cv;
            p += __shfl_xor_sync(0xffffffffu, p, 8);
            p += __shfl_xor_sync(0xffffffffu, p, 4);
            p += __shfl_xor_sync(0xffffffffu, p, 2);
            p += __shfl_xor_sync(0xffffffffu, p, 1);
            if (n == 0) yb[t][dloc] = p;
        }
        __syncthreads();

        // epilogue: y = (y_scan + u*D) * silu(z)  -> fp16 hi/lo
        for (int i = tid; i < SCAN_T * SCAN_D; i += 128) {
            int tt = i >> 3, dd = i & 7;
            size_t row = (size_t)(b * LL + l0 + tt);
            float zz = z_s[tt][dd];
            float sz = zz / (1.f + __expf(-zz));
            float yv = fmaf(u_s[tt][dd], Dvec[d0 + dd], yb[tt][dd]) * sz;
            __half hv = __float2half(yv);
            __half lv = __float2half(yv - __half2float(hv));
            g_ah[row * DI + d0 + dd] = hv;
            g_al[row * DI + d0 + dd] = lv;
        }
        __syncthreads();
    }
}

// ---------------------------------------------------------------------------
// residual + LayerNorm over DM=768
// ---------------------------------------------------------------------------
__global__ void __launch_bounds__(256) resid_ln(
    const float* __restrict__ x, const float* __restrict__ w,
    const float* __restrict__ bln, float* __restrict__ out)
{
    const int row = blockIdx.x;
    const float* o  = g_ob + (size_t)row * DM;
    const float* xr = x    + (size_t)row * DM;

    float v[3];
    float s = 0.f, ss = 0.f;
#pragma unroll
    for (int i = 0; i < 3; ++i) {
        int c = threadIdx.x + i * 256;
        v[i] = o[c] + xr[c];
        s += v[i];
        ss += v[i] * v[i];
    }
#pragma unroll
    for (int off = 16; off; off >>= 1) {
        s  += __shfl_xor_sync(0xffffffffu, s,  off);
        ss += __shfl_xor_sync(0xffffffffu, ss, off);
    }
    __shared__ float sbuf[16];
    int warp = threadIdx.x >> 5, lane = threadIdx.x & 31;
    if (lane == 0) { sbuf[warp] = s; sbuf[8 + warp] = ss; }
    __syncthreads();
    float S = 0.f, SS = 0.f;
#pragma unroll
    for (int i = 0; i < 8; ++i) { S += sbuf[i]; SS += sbuf[8 + i]; }
    float mean = S * (1.f / DM);
    float var  = SS * (1.f / DM) - mean * mean;
    float rstd = rsqrtf(var + 1e-5f);
#pragma unroll
    for (int i = 0; i < 3; ++i) {
        int c = threadIdx.x + i * 256;
        out[(size_t)row * DM + c] = (v[i] - mean) * rstd * w[c] + bln[c];
    }
}

// ---------------------------------------------------------------------------
extern "C" void kernel_launch(void* const* d_in, const int* in_sizes, int n_in,
                              void* d_out, int out_size)
{
    const float* x       = (const float*)d_in[0];
    const float* in_w    = (const float*)d_in[1];
    const float* conv_w  = (const float*)d_in[2];
    const float* conv_b  = (const float*)d_in[3];
    const float* xproj_w = (const float*)d_in[4];
    const float* dt_w    = (const float*)d_in[5];
    const float* dt_b    = (const float*)d_in[6];
    const float* A_log   = (const float*)d_in[7];
    const float* Dv      = (const float*)d_in[8];
    const float* out_w   = (const float*)d_in[9];
    const float* ln_w    = (const float*)d_in[10];
    const float* ln_b    = (const float*)d_in[11];
    float* out = (float*)d_out;

    float *p_xz, *p_ob;
    cudaGetSymbolAddress((void**)&p_xz, g_xz);
    cudaGetSymbolAddress((void**)&p_ob, g_ob);
    __half *p_ah, *p_al, *p_bh;
    cudaGetSymbolAddress((void**)&p_ah, g_ah);
    cudaGetSymbolAddress((void**)&p_al, g_al);
    cudaGetSymbolAddress((void**)&p_bh, g_bh);

    cudaFuncSetAttribute(gemm_f16, cudaFuncAttributeMaxDynamicSharedMemorySize,
                         GEMM_SMEM);

    // 0a) split x -> A hi/lo (fp16)
    {
        int n4 = MROWS * DM / 4;
        split_kernel<<<(n4 + 255) / 256, 256>>>(
            (const float4*)x, (uint2*)p_ah, (uint2*)p_al, n4);
    }
    // 0b) convert in_proj_w -> B hi (fp16)
    {
        int n4 = 2 * DI * DM / 4;
        convert_kernel<<<(n4 + 255) / 256, 256>>>(
            (const float4*)in_w, (uint2*)p_bh, n4);
    }

    // 1) in_proj: xz = x @ in_proj_w^T   [4096, 3072]
    gemm_f16<<<dim3((2 * DI) / BN, MROWS / BM), 256, GEMM_SMEM>>>(
        p_ah, p_al, p_bh, p_xz, MROWS, 2 * DI, DM);

    // 2) depthwise causal conv + silu -> g_u
    conv_silu_kernel<<<(MROWS * DI + 255) / 256, 256>>>(conv_w, conv_b);

    // 3) x_proj -> g_xdbl [4096, 80]
    gemm_xproj<<<MROWS / 32, 256>>>(xproj_w);

    // 4) dt_proj + softplus -> g_dt
    dtproj_softplus<<<dim3(MROWS / 32, DI / 128), 256>>>(dt_w, dt_b);

    // 5) selective scan + skip + gate -> fp16 hi/lo A staging (fused split)
    scan_kernel<<<BB * (DI / SCAN_D), 128>>>(A_log, Dv);

    // 6a) convert out_proj_w -> B hi (fp16)
    {
        int n4 = DM * DI / 4;
        convert_kernel<<<(n4 + 255) / 256, 256>>>(
            (const float4*)out_w, (uint2*)p_bh, n4);
    }

    // 6b) out_proj: ob = y @ out_proj_w^T  [4096, 768]
    gemm_f16<<<dim3(DM / BN, MROWS / BM), 256, GEMM_SMEM>>>(
        p_ah, p_al, p_bh, p_ob, MROWS, DM, DI);

    // 7) residual + LayerNorm -> out
    resid_ln<<<MROWS, 256>>>(x, ln_w, ln_b, out);
}

// round 10
// speedup vs baseline: 1.9073x; 1.1986x over previous
#include <cuda_runtime.h>
#include <cuda_fp16.h>
#include <math.h>
#include <stdint.h>

// ---------------------------------------------------------------------------
// MambaBlock: B=2, L=2048, D_MODEL=768, D_INNER=1536, D_STATE=16, DT_RANK=48
// ---------------------------------------------------------------------------
#define BB   2
#define LL   2048
#define DM   768
#define DI   1536
#define NS   16
#define RK   48
#define MROWS (BB * LL)       // 4096
#define XP    80              // DT_RANK + 2*D_STATE

// ---------------- scratch (device globals; no allocation allowed) ----------
__device__ float g_xz  [MROWS * 2 * DI];   // in_proj output [4096, 3072]
__device__ float g_u   [MROWS * DI];       // conv+silu output
__device__ float g_xdbl[MROWS * XP];       // x_proj output [4096, 80]
__device__ float g_xp  [4 * MROWS * XP];   // x_proj split-K partials
__device__ float g_dt  [MROWS * DI];       // softplus(dt_proj)
__device__ float g_ob  [MROWS * DM];       // out_proj output
// fp16 staging for tensor GEMMs
__device__ __half g_ah [MROWS * DI];       // A hi  (max 4096x1536)
__device__ __half g_al [MROWS * DI];       // A lo
__device__ __half g_bh [2 * DI * DM];      // in_proj_w fp16
__device__ __half g_bh2[DM * DI];          // out_proj_w fp16

// ===========================================================================
// helpers
// ===========================================================================
__device__ __forceinline__ uint32_t smem_u32(const void* p) {
    uint32_t a;
    asm("{ .reg .u64 t; cvta.to.shared.u64 t, %1; cvt.u32.u64 %0, t; }"
        : "=r"(a) : "l"(p));
    return a;
}
__device__ __forceinline__ void ldsm_x4(uint32_t& r0, uint32_t& r1,
                                        uint32_t& r2, uint32_t& r3, uint32_t addr) {
    asm volatile("ldmatrix.sync.aligned.m8n8.x4.shared.b16 {%0,%1,%2,%3}, [%4];"
                 : "=r"(r0), "=r"(r1), "=r"(r2), "=r"(r3) : "r"(addr));
}
__device__ __forceinline__ void mma_f16(float* c, const uint32_t* a,
                                        uint32_t b0, uint32_t b1) {
    asm volatile(
        "mma.sync.aligned.m16n8k16.row.col.f32.f16.f16.f32 "
        "{%0,%1,%2,%3}, {%4,%5,%6,%7}, {%8,%9}, {%0,%1,%2,%3};"
        : "+f"(c[0]), "+f"(c[1]), "+f"(c[2]), "+f"(c[3])
        : "r"(a[0]), "r"(a[1]), "r"(a[2]), "r"(a[3]), "r"(b0), "r"(b1));
}
#define CP_ASYNC16(dst, src) \
    asm volatile("cp.async.cg.shared.global [%0], [%1], 16;" :: "r"(dst), "l"(src))
#define CP_COMMIT() asm volatile("cp.async.commit_group;" ::: "memory")
#define CP_WAIT0()  asm volatile("cp.async.wait_group 0;" ::: "memory")
#define CP_WAIT1()  asm volatile("cp.async.wait_group 1;" ::: "memory")

// fp16 hi/lo split of a float4
__device__ __forceinline__ void split4h(float4 v, uint2& hi, uint2& lo) {
    __half hx = __float2half(v.x), hy = __float2half(v.y);
    __half hz = __float2half(v.z), hw = __float2half(v.w);
    __half lx = __float2half(v.x - __half2float(hx));
    __half ly = __float2half(v.y - __half2float(hy));
    __half lz = __float2half(v.z - __half2float(hz));
    __half lw = __float2half(v.w - __half2float(hw));
    __half2 h01 = __halves2half2(hx, hy), h23 = __halves2half2(hz, hw);
    __half2 l01 = __halves2half2(lx, ly), l23 = __halves2half2(lz, lw);
    hi = make_uint2(*(uint32_t*)&h01, *(uint32_t*)&h23);
    lo = make_uint2(*(uint32_t*)&l01, *(uint32_t*)&l23);
}

__global__ void __launch_bounds__(256) split_kernel(
    const float4* __restrict__ src, uint2* __restrict__ hi,
    uint2* __restrict__ lo, int n4)
{
    int i = blockIdx.x * blockDim.x + threadIdx.x;
    if (i >= n4) return;
    uint2 h, l;
    split4h(src[i], h, l);
    hi[i] = h; lo[i] = l;
}
__global__ void __launch_bounds__(256) convert_kernel(
    const float4* __restrict__ src, uint2* __restrict__ hi, int n4)
{
    int i = blockIdx.x * blockDim.x + threadIdx.x;
    if (i >= n4) return;
    float4 v = src[i];
    __half2 h01 = __halves2half2(__float2half(v.x), __float2half(v.y));
    __half2 h23 = __halves2half2(__float2half(v.z), __float2half(v.w));
    hi[i] = make_uint2(*(uint32_t*)&h01, *(uint32_t*)&h23);
}

// ===========================================================================
// fp16 HMMA GEMM, 2-pass (A hi/lo, B single), 3-stage cp.async pipeline.
// CTA tile 128x128, BK=32. 256 threads = 8 warps, warp tile 32x64.
// ===========================================================================
#define BM 128
#define BN 128
#define BK 32
#define SROW 40                          // fp16/row (80B: LDSM conflict-free)
#define TILE_B (BM * SROW * 2)           // 10240 bytes per tile
#define STAGE_B (3 * TILE_B)             // 30720 bytes per stage (Ah, Al, Bh)
#define NSTAGE 3
#define GEMM_SMEM (NSTAGE * STAGE_B)     // 92160 bytes

__global__ void __launch_bounds__(256) gemm_f16(
    const __half* __restrict__ Ah, const __half* __restrict__ Al,
    const __half* __restrict__ Bh,
    float* __restrict__ C, int M, int N, int K)
{
    extern __shared__ char smem[];
    const uint32_t sbase = smem_u32(smem);

    const int tid  = threadIdx.x;
    const int wid  = tid >> 5;
    const int lane = tid & 31;
    const int bm = blockIdx.y * BM;
    const int bn = blockIdx.x * BN;

    const int wm = (wid & 3) * 32;
    const int wn = (wid >> 2) * 64;

    float acc[2][8][4];
#pragma unroll
    for (int i = 0; i < 2; ++i)
#pragma unroll
        for (int j = 0; j < 8; ++j)
#pragma unroll
            for (int k = 0; k < 4; ++k) acc[i][j][k] = 0.f;

    const int aRow = lane & 15;
    const int aKof = (lane >> 4) << 3;
    const int bRow = lane & 15;
    const int bKof = (lane >> 4) << 3;

    const __half* srcs[3] = {Ah, Al, Bh};
    const int nch = K / BK;

    auto load_stage = [&](int stage, int k0) {
#pragma unroll
        for (int p = 0; p < 6; ++p) {
            int chunk = p * 256 + tid;
            int tile  = chunk >> 9;          // 0..2
            int idx   = chunk & 511;
            int row   = idx >> 2;            // 0..127
            int part  = idx & 3;
            int grow  = (tile < 2 ? bm : bn) + row;
            const __half* src = srcs[tile] + (size_t)grow * K + k0 + part * 8;
            uint32_t dst = sbase + stage * STAGE_B + tile * TILE_B
                         + row * (SROW * 2) + part * 16;
            CP_ASYNC16(dst, src);
        }
        CP_COMMIT();
    };

    load_stage(0, 0);
    if (nch > 1) load_stage(1, BK);

    for (int ch = 0; ch < nch; ++ch) {
        if (ch + 1 < nch) { CP_WAIT1(); } else { CP_WAIT0(); }
        __syncthreads();
        if (ch + 2 < nch) load_stage((ch + 2) % NSTAGE, (ch + 2) * BK);

        const uint32_t base = sbase + (ch % NSTAGE) * STAGE_B;
        const uint32_t uAh = base;
        const uint32_t uAl = base + TILE_B;
        const uint32_t uBh = base + 2 * TILE_B;

#pragma unroll
        for (int ks = 0; ks < 2; ++ks) {
            const int kb = ks * 16;
            uint32_t Afh[2][4], Afl[2][4];
#pragma unroll
            for (int mt = 0; mt < 2; ++mt) {
                uint32_t off = (uint32_t)((wm + mt * 16 + aRow) * SROW + kb + aKof) * 2;
                ldsm_x4(Afh[mt][0], Afh[mt][1], Afh[mt][2], Afh[mt][3], uAh + off);
                ldsm_x4(Afl[mt][0], Afl[mt][1], Afl[mt][2], Afl[mt][3], uAl + off);
            }
#pragma unroll
            for (int nt2 = 0; nt2 < 4; ++nt2) {
                uint32_t b0, b1, b2, b3;
                uint32_t off = (uint32_t)((wn + nt2 * 16 + bRow) * SROW + kb + bKof) * 2;
                ldsm_x4(b0, b1, b2, b3, uBh + off);
#pragma unroll
                for (int mt = 0; mt < 2; ++mt) {
                    mma_f16(acc[mt][nt2 * 2],     Afh[mt], b0, b2);
                    mma_f16(acc[mt][nt2 * 2],     Afl[mt], b0, b2);
                    mma_f16(acc[mt][nt2 * 2 + 1], Afh[mt], b1, b3);
                    mma_f16(acc[mt][nt2 * 2 + 1], Afl[mt], b1, b3);
                }
            }
        }
        __syncthreads();
    }

    const int g  = lane >> 2;
    const int cc = (lane & 3) * 2;
#pragma unroll
    for (int mt = 0; mt < 2; ++mt) {
#pragma unroll
        for (int nt = 0; nt < 8; ++nt) {
            int row0 = bm + wm + mt * 16 + g;
            int col  = bn + wn + nt * 8 + cc;
            *reinterpret_cast<float2*>(C + (size_t)row0 * N + col) =
                make_float2(acc[mt][nt][0], acc[mt][nt][1]);
            *reinterpret_cast<float2*>(C + (size_t)(row0 + 8) * N + col) =
                make_float2(acc[mt][nt][2], acc[mt][nt][3]);
        }
    }
}

// ---------------------------------------------------------------------------
// Depthwise causal conv (k=4) + bias + silu over u = xz[:, :, 0:DI]
// ---------------------------------------------------------------------------
__global__ void __launch_bounds__(256) conv_silu_kernel(
    const float* __restrict__ conv_w, const float* __restrict__ conv_b)
{
    int idx = blockIdx.x * blockDim.x + threadIdx.x;
    if (idx >= MROWS * DI) return;
    int d = idx % DI;
    int l = (idx / DI) % LL;
    int b = idx / (DI * LL);

    float acc = conv_b[d];
#pragma unroll
    for (int j = 0; j < 4; ++j) {
        int ll = l - 3 + j;
        if (ll >= 0)
            acc = fmaf(conv_w[d * 4 + j],
                       g_xz[(size_t)(b * LL + ll) * (2 * DI) + d], acc);
    }
    g_u[idx] = acc / (1.f + __expf(-acc));
}

// ---------------------------------------------------------------------------
// x_proj split-K: partial[ks][4096,80] = u[:, ks*384:(ks+1)*384] @ W_slice^T
// grid (128, 4); then reduce.
// ---------------------------------------------------------------------------
__global__ void __launch_bounds__(256) gemm_xproj_part(
    const float* __restrict__ W)
{
    __shared__ float As[32][33];   // [k][m]
    __shared__ float Ws[32][81];   // [k][n]

    const int tid = threadIdx.x;
    const int m0 = blockIdx.x * 32;
    const int kbase = blockIdx.y * (DI / 4);
    const int tx = tid & 15;       // n: 5 each
    const int ty = tid >> 4;       // m: 2 each

    float acc[2][5] = {};

    for (int kc = 0; kc < DI / 4; kc += 32) {
        int k0 = kbase + kc;
        for (int i = tid; i < 32 * 32; i += 256) {
            int m = i >> 5, k = i & 31;
            As[k][m] = g_u[(size_t)(m0 + m) * DI + k0 + k];
        }
        for (int i = tid; i < 80 * 32; i += 256) {
            int nn = i >> 5, k = i & 31;
            Ws[k][nn] = W[(size_t)nn * DI + k0 + k];
        }
        __syncthreads();
#pragma unroll
        for (int k = 0; k < 32; ++k) {
            float a0 = As[k][ty * 2];
            float a1 = As[k][ty * 2 + 1];
#pragma unroll
            for (int j = 0; j < 5; ++j) {
                float w = Ws[k][tx * 5 + j];
                acc[0][j] = fmaf(a0, w, acc[0][j]);
                acc[1][j] = fmaf(a1, w, acc[1][j]);
            }
        }
        __syncthreads();
    }
    float* dst = g_xp + (size_t)blockIdx.y * MROWS * XP;
#pragma unroll
    for (int i = 0; i < 2; ++i)
#pragma unroll
        for (int j = 0; j < 5; ++j)
            dst[(size_t)(m0 + ty * 2 + i) * XP + tx * 5 + j] = acc[i][j];
}

__global__ void __launch_bounds__(256) xproj_reduce(int n4)
{
    int i = blockIdx.x * blockDim.x + threadIdx.x;
    if (i >= n4) return;
    const float4* p = (const float4*)g_xp;
    const int S = MROWS * XP / 4;
    float4 a = p[i], b = p[i + S], c = p[i + 2 * S], d = p[i + 3 * S];
    float4 r = make_float4(a.x + b.x + c.x + d.x, a.y + b.y + c.y + d.y,
                           a.z + b.z + c.z + d.z, a.w + b.w + c.w + d.w);
    ((float4*)g_xdbl)[i] = r;
}

// ---------------------------------------------------------------------------
// dt_proj (K=48) + bias + softplus. 64 m x 128 d per block, 4m x 8d / thread.
// ---------------------------------------------------------------------------
__global__ void __launch_bounds__(256) dtproj_softplus(
    const float* __restrict__ W, const float* __restrict__ bias)
{
    __shared__ __align__(16) float Ls[RK][68];    // [r][m]
    __shared__ __align__(16) float Ws[RK][132];   // [r][d]

    const int tid = threadIdx.x;
    const int m0 = blockIdx.x * 64;
    const int d0 = blockIdx.y * 128;

    for (int i = tid; i < 64 * RK; i += 256) {
        int m = i / RK, r = i - m * RK;
        Ls[r][m] = g_xdbl[(size_t)(m0 + m) * XP + r];
    }
    for (int i = tid; i < 128 * RK; i += 256) {
        int d = i / RK, r = i - d * RK;
        Ws[r][d] = W[(size_t)(d0 + d) * RK + r];
    }
    __syncthreads();

    const int tx = tid & 15;   // d: 8 each
    const int ty = tid >> 4;   // m: 4 each
    float acc[4][8] = {};
#pragma unroll
    for (int r = 0; r < RK; ++r) {
        float4 a  = *reinterpret_cast<const float4*>(&Ls[r][ty * 4]);
        float4 w0 = *reinterpret_cast<const float4*>(&Ws[r][tx * 8]);
        float4 w1 = *reinterpret_cast<const float4*>(&Ws[r][tx * 8 + 4]);
        const float av[4] = {a.x, a.y, a.z, a.w};
        const float wv[8] = {w0.x, w0.y, w0.z, w0.w, w1.x, w1.y, w1.z, w1.w};
#pragma unroll
        for (int i = 0; i < 4; ++i)
#pragma unroll
            for (int j = 0; j < 8; ++j)
                acc[i][j] = fmaf(av[i], wv[j], acc[i][j]);
    }
    float bv[8];
#pragma unroll
    for (int j = 0; j < 8; ++j) bv[j] = bias[d0 + tx * 8 + j];
#pragma unroll
    for (int i = 0; i < 4; ++i) {
        float o[8];
#pragma unroll
        for (int j = 0; j < 8; ++j) {
            float v = acc[i][j] + bv[j];
            o[j] = (v > 20.f) ? v : __logf(1.f + __expf(v));
        }
        float* dst = &g_dt[(size_t)(m0 + ty * 4 + i) * DI + d0 + tx * 8];
        *reinterpret_cast<float4*>(dst)     = make_float4(o[0], o[1], o[2], o[3]);
        *reinterpret_cast<float4*>(dst + 4) = make_float4(o[4], o[5], o[6], o[7]);
    }
}

// ---------------------------------------------------------------------------
// Selective scan + skip + gate, fused; emits y as fp16 hi/lo to GEMM staging.
// Block = 128 threads = 8 d x 16 states; grid = B * DI/8 = 384.
// ---------------------------------------------------------------------------
#define SCAN_T 32
#define SCAN_D 8
__global__ void __launch_bounds__(128) scan_kernel(
    const float* __restrict__ A_log, const float* __restrict__ Dvec)
{
    const int b  = blockIdx.x / (DI / SCAN_D);
    const int d0 = (blockIdx.x % (DI / SCAN_D)) * SCAN_D;
    const int tid  = threadIdx.x;
    const int lane = tid & 31;
    const int warp = tid >> 5;
    const int n    = lane & 15;
    const int dloc = (warp << 1) | (lane >> 4);
    const int d    = d0 + dloc;

    const float a = -__expf(A_log[d * NS + n]);

    __shared__ float dt_s[SCAN_T][SCAN_D];
    __shared__ float u_s [SCAN_T][SCAN_D];
    __shared__ float z_s [SCAN_T][SCAN_D];
    __shared__ float B_s [SCAN_T][16];
    __shared__ float C_s [SCAN_T][16];
    __shared__ float yb  [SCAN_T][SCAN_D];

    float h = 0.f;

    for (int l0 = 0; l0 < LL; l0 += SCAN_T) {
        for (int i = tid; i < SCAN_T * SCAN_D; i += 128) {
            int tt = i >> 3, dd = i & 7;
            size_t row = (size_t)(b * LL + l0 + tt);
            dt_s[tt][dd] = g_dt[row * DI + d0 + dd];
            u_s [tt][dd] = g_u [row * DI + d0 + dd];
            z_s [tt][dd] = g_xz[row * (2 * DI) + DI + d0 + dd];
        }
        for (int i = tid; i < SCAN_T * 16; i += 128) {
            int tt = i >> 4, nn = i & 15;
            size_t row = (size_t)(b * LL + l0 + tt);
            B_s[tt][nn] = g_xdbl[row * XP + RK + nn];
            C_s[tt][nn] = g_xdbl[row * XP + RK + NS + nn];
        }
        __syncthreads();

#pragma unroll 8
        for (int t = 0; t < SCAN_T; ++t) {
            float dtv = dt_s[t][dloc];
            float uv  = u_s [t][dloc];
            float Bv  = B_s [t][n];
            float Cv  = C_s [t][n];
            h = fmaf(h, __expf(dtv * a), dtv * uv * Bv);
            float p = h * Cv;
            p += __shfl_xor_sync(0xffffffffu, p, 8);
            p += __shfl_xor_sync(0xffffffffu, p, 4);
            p += __shfl_xor_sync(0xffffffffu, p, 2);
            p += __shfl_xor_sync(0xffffffffu, p, 1);
            if (n == 0) yb[t][dloc] = p;
        }
        __syncthreads();

        for (int i = tid; i < SCAN_T * SCAN_D; i += 128) {
            int tt = i >> 3, dd = i & 7;
            size_t row = (size_t)(b * LL + l0 + tt);
            float zz = z_s[tt][dd];
            float sz = zz / (1.f + __expf(-zz));
            float yv = fmaf(u_s[tt][dd], Dvec[d0 + dd], yb[tt][dd]) * sz;
            __half hv = __float2half(yv);
            __half lv = __float2half(yv - __half2float(hv));
            g_ah[row * DI + d0 + dd] = hv;
            g_al[row * DI + d0 + dd] = lv;
        }
        __syncthreads();
    }
}

// ---------------------------------------------------------------------------
// residual + LayerNorm over DM=768
// ---------------------------------------------------------------------------
__global__ void __launch_bounds__(256) resid_ln(
    const float* __restrict__ x, const float* __restrict__ w,
    const float* __restrict__ bln, float* __restrict__ out)
{
    const int row = blockIdx.x;
    const float* o  = g_ob + (size_t)row * DM;
    const float* xr = x    + (size_t)row * DM;

    float v[3];
    float s = 0.f, ss = 0.f;
#pragma unroll
    for (int i = 0; i < 3; ++i) {
        int c = threadIdx.x + i * 256;
        v[i] = o[c] + xr[c];
        s += v[i];
        ss += v[i] * v[i];
    }
#pragma unroll
    for (int off = 16; off; off >>= 1) {
        s  += __shfl_xor_sync(0xffffffffu, s,  off);
        ss += __shfl_xor_sync(0xffffffffu, ss, off);
    }
    __shared__ float sbuf[16];
    int warp = threadIdx.x >> 5, lane = threadIdx.x & 31;
    if (lane == 0) { sbuf[warp] = s; sbuf[8 + warp] = ss; }
    __syncthreads();
    float S = 0.f, SS = 0.f;
#pragma unroll
    for (int i = 0; i < 8; ++i) { S += sbuf[i]; SS += sbuf[8 + i]; }
    float mean = S * (1.f / DM);
    float var  = SS * (1.f / DM) - mean * mean;
    float rstd = rsqrtf(var + 1e-5f);
#pragma unroll
    for (int i = 0; i < 3; ++i) {
        int c = threadIdx.x + i * 256;
        out[(size_t)row * DM + c] = (v[i] - mean) * rstd * w[c] + bln[c];
    }
}

// ---------------------------------------------------------------------------
extern "C" void kernel_launch(void* const* d_in, const int* in_sizes, int n_in,
                              void* d_out, int out_size)
{
    const float* x       = (const float*)d_in[0];
    const float* in_w    = (const float*)d_in[1];
    const float* conv_w  = (const float*)d_in[2];
    const float* conv_b  = (const float*)d_in[3];
    const float* xproj_w = (const float*)d_in[4];
    const float* dt_w    = (const float*)d_in[5];
    const float* dt_b    = (const float*)d_in[6];
    const float* A_log   = (const float*)d_in[7];
    const float* Dv      = (const float*)d_in[8];
    const float* out_w   = (const float*)d_in[9];
    const float* ln_w    = (const float*)d_in[10];
    const float* ln_b    = (const float*)d_in[11];
    float* out = (float*)d_out;

    float *p_xz, *p_ob;
    cudaGetSymbolAddress((void**)&p_xz, g_xz);
    cudaGetSymbolAddress((void**)&p_ob, g_ob);
    __half *p_ah, *p_al, *p_bh, *p_bh2;
    cudaGetSymbolAddress((void**)&p_ah,  g_ah);
    cudaGetSymbolAddress((void**)&p_al,  g_al);
    cudaGetSymbolAddress((void**)&p_bh,  g_bh);
    cudaGetSymbolAddress((void**)&p_bh2, g_bh2);

    cudaFuncSetAttribute(gemm_f16, cudaFuncAttributeMaxDynamicSharedMemorySize,
                         GEMM_SMEM);

    // (1) split x -> A hi/lo (fp16)
    {
        int n4 = MROWS * DM / 4;
        split_kernel<<<(n4 + 255) / 256, 256>>>(
            (const float4*)x, (uint2*)p_ah, (uint2*)p_al, n4);
    }
    // (2) convert in_proj_w -> fp16
    {
        int n4 = 2 * DI * DM / 4;
        convert_kernel<<<(n4 + 255) / 256, 256>>>(
            (const float4*)in_w, (uint2*)p_bh, n4);
    }
    // (3) convert out_proj_w -> fp16 (early, so gemm1 lands on profile slot 4)
    {
        int n4 = DM * DI / 4;
        convert_kernel<<<(n4 + 255) / 256, 256>>>(
            (const float4*)out_w, (uint2*)p_bh2, n4);
    }

    // (4) in_proj: xz = x @ in_proj_w^T   [4096, 3072]   <-- ncu capture slot
    gemm_f16<<<dim3((2 * DI) / BN, MROWS / BM), 256, GEMM_SMEM>>>(
        p_ah, p_al, p_bh, p_xz, MROWS, 2 * DI, DM);

    // (5) depthwise causal conv + silu -> g_u
    conv_silu_kernel<<<(MROWS * DI + 255) / 256, 256>>>(conv_w, conv_b);

    // (6) x_proj split-K partials -> g_xp
    gemm_xproj_part<<<dim3(MROWS / 32, 4), 256>>>(xproj_w);
    // (7) reduce partials -> g_xdbl
    {
        int n4 = MROWS * XP / 4;
        xproj_reduce<<<(n4 + 255) / 256, 256>>>(n4);
    }

    // (8) dt_proj + softplus -> g_dt
    dtproj_softplus<<<dim3(MROWS / 64, DI / 128), 256>>>(dt_w, dt_b);

    // (9) selective scan + skip + gate -> fp16 hi/lo A staging
    scan_kernel<<<BB * (DI / SCAN_D), 128>>>(A_log, Dv);

    // (10) out_proj: ob = y @ out_proj_w^T  [4096, 768]
    gemm_f16<<<dim3(DM / BN, MROWS / BM), 256, GEMM_SMEM>>>(
        p_ah, p_al, p_bh2, p_ob, MROWS, DM, DI);

    // (11) residual + LayerNorm -> out
    resid_ln<<<MROWS, 256>>>(x, ln_w, ln_b, out);
}

// round 11
// speedup vs baseline: 2.5062x; 1.3140x over previous
#include <cuda_runtime.h>
#include <cuda_fp16.h>
#include <math.h>
#include <stdint.h>

// ---------------------------------------------------------------------------
// MambaBlock: B=2, L=2048, D_MODEL=768, D_INNER=1536, D_STATE=16, DT_RANK=48
// ---------------------------------------------------------------------------
#define BB   2
#define LL   2048
#define DM   768
#define DI   1536
#define NS   16
#define RK   48
#define MROWS (BB * LL)       // 4096
#define XP    80              // DT_RANK + 2*D_STATE
#define SEG   16
#define SLEN  (LL / SEG)      // 128

// ---------------- scratch (device globals; no allocation allowed) ----------
__device__ float g_xz  [MROWS * 2 * DI];   // in_proj output [4096, 3072]
__device__ float g_u   [MROWS * DI];       // conv+silu output
__device__ float g_xdbl[MROWS * XP];       // x_proj output [4096, 80]
__device__ float g_xp  [4 * MROWS * XP];   // x_proj split-K partials
__device__ float g_dt  [MROWS * DI];       // softplus(dt_proj)
__device__ float g_ob  [MROWS * DM];       // out_proj partial 0
__device__ float g_ob2 [MROWS * DM];       // out_proj partial 1
// segmented-scan state
__device__ float g_hend[BB * SEG * DI * NS];
__device__ float g_pend[BB * SEG * DI * NS];
__device__ float g_hin [BB * SEG * DI * NS];
// fp16 staging for tensor GEMMs
__device__ __half g_ah [MROWS * DI];       // A hi
__device__ __half g_al [MROWS * DI];       // A lo
__device__ __half g_bh [2 * DI * DM];      // in_proj_w fp16
__device__ __half g_bh2[DM * DI];          // out_proj_w fp16

// ===========================================================================
// helpers
// ===========================================================================
__device__ __forceinline__ uint32_t smem_u32(const void* p) {
    uint32_t a;
    asm("{ .reg .u64 t; cvta.to.shared.u64 t, %1; cvt.u32.u64 %0, t; }"
        : "=r"(a) : "l"(p));
    return a;
}
__device__ __forceinline__ void ldsm_x4(uint32_t& r0, uint32_t& r1,
                                        uint32_t& r2, uint32_t& r3, uint32_t addr) {
    asm volatile("ldmatrix.sync.aligned.m8n8.x4.shared.b16 {%0,%1,%2,%3}, [%4];"
                 : "=r"(r0), "=r"(r1), "=r"(r2), "=r"(r3) : "r"(addr));
}
__device__ __forceinline__ void mma_f16(float* c, const uint32_t* a,
                                        uint32_t b0, uint32_t b1) {
    asm volatile(
        "mma.sync.aligned.m16n8k16.row.col.f32.f16.f16.f32 "
        "{%0,%1,%2,%3}, {%4,%5,%6,%7}, {%8,%9}, {%0,%1,%2,%3};"
        : "+f"(c[0]), "+f"(c[1]), "+f"(c[2]), "+f"(c[3])
        : "r"(a[0]), "r"(a[1]), "r"(a[2]), "r"(a[3]), "r"(b0), "r"(b1));
}
#define CP_ASYNC16(dst, src) \
    asm volatile("cp.async.cg.shared.global [%0], [%1], 16;" :: "r"(dst), "l"(src))
#define CP_COMMIT() asm volatile("cp.async.commit_group;" ::: "memory")
#define CP_WAIT0()  asm volatile("cp.async.wait_group 0;" ::: "memory")
#define CP_WAIT1()  asm volatile("cp.async.wait_group 1;" ::: "memory")

__device__ __forceinline__ void split4h(float4 v, uint2& hi, uint2& lo) {
    __half hx = __float2half(v.x), hy = __float2half(v.y);
    __half hz = __float2half(v.z), hw = __float2half(v.w);
    __half lx = __float2half(v.x - __half2float(hx));
    __half ly = __float2half(v.y - __half2float(hy));
    __half lz = __float2half(v.z - __half2float(hz));
    __half lw = __float2half(v.w - __half2float(hw));
    __half2 h01 = __halves2half2(hx, hy), h23 = __halves2half2(hz, hw);
    __half2 l01 = __halves2half2(lx, ly), l23 = __halves2half2(lz, lw);
    hi = make_uint2(*(uint32_t*)&h01, *(uint32_t*)&h23);
    lo = make_uint2(*(uint32_t*)&l01, *(uint32_t*)&l23);
}

__global__ void __launch_bounds__(256) split_kernel(
    const float4* __restrict__ src, uint2* __restrict__ hi,
    uint2* __restrict__ lo, int n4)
{
    int i = blockIdx.x * blockDim.x + threadIdx.x;
    if (i >= n4) return;
    uint2 h, l;
    split4h(src[i], h, l);
    hi[i] = h; lo[i] = l;
}
__global__ void __launch_bounds__(256) convert_kernel(
    const float4* __restrict__ src, uint2* __restrict__ hi, int n4)
{
    int i = blockIdx.x * blockDim.x + threadIdx.x;
    if (i >= n4) return;
    float4 v = src[i];
    __half2 h01 = __halves2half2(__float2half(v.x), __float2half(v.y));
    __half2 h23 = __halves2half2(__float2half(v.z), __float2half(v.w));
    hi[i] = make_uint2(*(uint32_t*)&h01, *(uint32_t*)&h23);
}

// ===========================================================================
// fp16 HMMA GEMM, 2-pass (A hi/lo, B single), 3-stage cp.async pipeline.
// CTA tile 128x128, BK=32. ld = row stride of A and B. blockIdx.z selects a
// K-slice of width K and the output buffer (C or C2) for split-K.
// ===========================================================================
#define BM 128
#define BN 128
#define BK 32
#define SROW 40
#define TILE_B (BM * SROW * 2)
#define STAGE_B (3 * TILE_B)
#define NSTAGE 3
#define GEMM_SMEM (NSTAGE * STAGE_B)

__global__ void __launch_bounds__(256) gemm_f16(
    const __half* __restrict__ Ah, const __half* __restrict__ Al,
    const __half* __restrict__ Bh,
    float* __restrict__ C, float* __restrict__ C2,
    int M, int N, int K, int ld)
{
    extern __shared__ char smem[];
    const uint32_t sbase = smem_u32(smem);

    const int tid  = threadIdx.x;
    const int wid  = tid >> 5;
    const int lane = tid & 31;
    const int bm = blockIdx.y * BM;
    const int bn = blockIdx.x * BN;
    const int zk = blockIdx.z * K;        // column offset for split-K
    float* Co = blockIdx.z ? C2 : C;

    const int wm = (wid & 3) * 32;
    const int wn = (wid >> 2) * 64;

    float acc[2][8][4];
#pragma unroll
    for (int i = 0; i < 2; ++i)
#pragma unroll
        for (int j = 0; j < 8; ++j)
#pragma unroll
            for (int k = 0; k < 4; ++k) acc[i][j][k] = 0.f;

    const int aRow = lane & 15;
    const int aKof = (lane >> 4) << 3;
    const int bRow = lane & 15;
    const int bKof = (lane >> 4) << 3;

    const __half* srcs[3] = {Ah, Al, Bh};
    const int nch = K / BK;

    auto load_stage = [&](int stage, int k0) {
#pragma unroll
        for (int p = 0; p < 6; ++p) {
            int chunk = p * 256 + tid;
            int tile  = chunk >> 9;
            int idx   = chunk & 511;
            int row   = idx >> 2;
            int part  = idx & 3;
            int grow  = (tile < 2 ? bm : bn) + row;
            const __half* src = srcs[tile] + (size_t)grow * ld + zk + k0 + part * 8;
            uint32_t dst = sbase + stage * STAGE_B + tile * TILE_B
                         + row * (SROW * 2) + part * 16;
            CP_ASYNC16(dst, src);
        }
        CP_COMMIT();
    };

    load_stage(0, 0);
    if (nch > 1) load_stage(1, BK);

    for (int ch = 0; ch < nch; ++ch) {
        if (ch + 1 < nch) { CP_WAIT1(); } else { CP_WAIT0(); }
        __syncthreads();
        if (ch + 2 < nch) load_stage((ch + 2) % NSTAGE, (ch + 2) * BK);

        const uint32_t base = sbase + (ch % NSTAGE) * STAGE_B;
        const uint32_t uAh = base;
        const uint32_t uAl = base + TILE_B;
        const uint32_t uBh = base + 2 * TILE_B;

#pragma unroll
        for (int ks = 0; ks < 2; ++ks) {
            const int kb = ks * 16;
            uint32_t Afh[2][4], Afl[2][4];
#pragma unroll
            for (int mt = 0; mt < 2; ++mt) {
                uint32_t off = (uint32_t)((wm + mt * 16 + aRow) * SROW + kb + aKof) * 2;
                ldsm_x4(Afh[mt][0], Afh[mt][1], Afh[mt][2], Afh[mt][3], uAh + off);
                ldsm_x4(Afl[mt][0], Afl[mt][1], Afl[mt][2], Afl[mt][3], uAl + off);
            }
#pragma unroll
            for (int nt2 = 0; nt2 < 4; ++nt2) {
                uint32_t b0, b1, b2, b3;
                uint32_t off = (uint32_t)((wn + nt2 * 16 + bRow) * SROW + kb + bKof) * 2;
                ldsm_x4(b0, b1, b2, b3, uBh + off);
#pragma unroll
                for (int mt = 0; mt < 2; ++mt) {
                    mma_f16(acc[mt][nt2 * 2],     Afh[mt], b0, b2);
                    mma_f16(acc[mt][nt2 * 2],     Afl[mt], b0, b2);
                    mma_f16(acc[mt][nt2 * 2 + 1], Afh[mt], b1, b3);
                    mma_f16(acc[mt][nt2 * 2 + 1], Afl[mt], b1, b3);
                }
            }
        }
        __syncthreads();
    }

    const int g  = lane >> 2;
    const int cc = (lane & 3) * 2;
#pragma unroll
    for (int mt = 0; mt < 2; ++mt) {
#pragma unroll
        for (int nt = 0; nt < 8; ++nt) {
            int row0 = bm + wm + mt * 16 + g;
            int col  = bn + wn + nt * 8 + cc;
            *reinterpret_cast<float2*>(Co + (size_t)row0 * N + col) =
                make_float2(acc[mt][nt][0], acc[mt][nt][1]);
            *reinterpret_cast<float2*>(Co + (size_t)(row0 + 8) * N + col) =
                make_float2(acc[mt][nt][2], acc[mt][nt][3]);
        }
    }
}

// ---------------------------------------------------------------------------
// Depthwise causal conv (k=4) + bias + silu over u = xz[:, :, 0:DI]
// ---------------------------------------------------------------------------
__global__ void __launch_bounds__(256) conv_silu_kernel(
    const float* __restrict__ conv_w, const float* __restrict__ conv_b)
{
    int idx = blockIdx.x * blockDim.x + threadIdx.x;
    if (idx >= MROWS * DI) return;
    int d = idx % DI;
    int l = (idx / DI) % LL;
    int b = idx / (DI * LL);

    float acc = conv_b[d];
#pragma unroll
    for (int j = 0; j < 4; ++j) {
        int ll = l - 3 + j;
        if (ll >= 0)
            acc = fmaf(conv_w[d * 4 + j],
                       g_xz[(size_t)(b * LL + ll) * (2 * DI) + d], acc);
    }
    g_u[idx] = acc / (1.f + __expf(-acc));
}

// ---------------------------------------------------------------------------
// x_proj split-K partials + reduce
// ---------------------------------------------------------------------------
__global__ void __launch_bounds__(256) gemm_xproj_part(
    const float* __restrict__ W)
{
    __shared__ float As[32][33];
    __shared__ float Ws[32][81];

    const int tid = threadIdx.x;
    const int m0 = blockIdx.x * 32;
    const int kbase = blockIdx.y * (DI / 4);
    const int tx = tid & 15;
    const int ty = tid >> 4;

    float acc[2][5] = {};

    for (int kc = 0; kc < DI / 4; kc += 32) {
        int k0 = kbase + kc;
        for (int i = tid; i < 32 * 32; i += 256) {
            int m = i >> 5, k = i & 31;
            As[k][m] = g_u[(size_t)(m0 + m) * DI + k0 + k];
        }
        for (int i = tid; i < 80 * 32; i += 256) {
            int nn = i >> 5, k = i & 31;
            Ws[k][nn] = W[(size_t)nn * DI + k0 + k];
        }
        __syncthreads();
#pragma unroll
        for (int k = 0; k < 32; ++k) {
            float a0 = As[k][ty * 2];
            float a1 = As[k][ty * 2 + 1];
#pragma unroll
            for (int j = 0; j < 5; ++j) {
                float w = Ws[k][tx * 5 + j];
                acc[0][j] = fmaf(a0, w, acc[0][j]);
                acc[1][j] = fmaf(a1, w, acc[1][j]);
            }
        }
        __syncthreads();
    }
    float* dst = g_xp + (size_t)blockIdx.y * MROWS * XP;
#pragma unroll
    for (int i = 0; i < 2; ++i)
#pragma unroll
        for (int j = 0; j < 5; ++j)
            dst[(size_t)(m0 + ty * 2 + i) * XP + tx * 5 + j] = acc[i][j];
}

__global__ void __launch_bounds__(256) xproj_reduce(int n4)
{
    int i = blockIdx.x * blockDim.x + threadIdx.x;
    if (i >= n4) return;
    const float4* p = (const float4*)g_xp;
    const int S = MROWS * XP / 4;
    float4 a = p[i], b = p[i + S], c = p[i + 2 * S], d = p[i + 3 * S];
    ((float4*)g_xdbl)[i] = make_float4(a.x + b.x + c.x + d.x, a.y + b.y + c.y + d.y,
                                       a.z + b.z + c.z + d.z, a.w + b.w + c.w + d.w);
}

// ---------------------------------------------------------------------------
// dt_proj (K=48) + bias + softplus. 64 m x 128 d per block.
// ---------------------------------------------------------------------------
__global__ void __launch_bounds__(256) dtproj_softplus(
    const float* __restrict__ W, const float* __restrict__ bias)
{
    __shared__ __align__(16) float Ls[RK][68];
    __shared__ __align__(16) float Ws[RK][132];

    const int tid = threadIdx.x;
    const int m0 = blockIdx.x * 64;
    const int d0 = blockIdx.y * 128;

    for (int i = tid; i < 64 * RK; i += 256) {
        int m = i / RK, r = i - m * RK;
        Ls[r][m] = g_xdbl[(size_t)(m0 + m) * XP + r];
    }
    for (int i = tid; i < 128 * RK; i += 256) {
        int d = i / RK, r = i - d * RK;
        Ws[r][d] = W[(size_t)(d0 + d) * RK + r];
    }
    __syncthreads();

    const int tx = tid & 15;
    const int ty = tid >> 4;
    float acc[4][8] = {};
#pragma unroll
    for (int r = 0; r < RK; ++r) {
        float4 a  = *reinterpret_cast<const float4*>(&Ls[r][ty * 4]);
        float4 w0 = *reinterpret_cast<const float4*>(&Ws[r][tx * 8]);
        float4 w1 = *reinterpret_cast<const float4*>(&Ws[r][tx * 8 + 4]);
        const float av[4] = {a.x, a.y, a.z, a.w};
        const float wv[8] = {w0.x, w0.y, w0.z, w0.w, w1.x, w1.y, w1.z, w1.w};
#pragma unroll
        for (int i = 0; i < 4; ++i)
#pragma unroll
            for (int j = 0; j < 8; ++j)
                acc[i][j] = fmaf(av[i], wv[j], acc[i][j]);
    }
    float bv[8];
#pragma unroll
    for (int j = 0; j < 8; ++j) bv[j] = bias[d0 + tx * 8 + j];
#pragma unroll
    for (int i = 0; i < 4; ++i) {
        float o[8];
#pragma unroll
        for (int j = 0; j < 8; ++j) {
            float v = acc[i][j] + bv[j];
            o[j] = (v > 20.f) ? v : __logf(1.f + __expf(v));
        }
        float* dst = &g_dt[(size_t)(m0 + ty * 4 + i) * DI + d0 + tx * 8];
        *reinterpret_cast<float4*>(dst)     = make_float4(o[0], o[1], o[2], o[3]);
        *reinterpret_cast<float4*>(dst + 4) = make_float4(o[4], o[5], o[6], o[7]);
    }
}

// ---------------------------------------------------------------------------
// Segmented selective scan.
// Layout per block: 128 threads = 8 d x 16 n. grid = BB*SEG*(DI/8) = 6144.
// ---------------------------------------------------------------------------
#define SCAN_T 32
#define SCAN_D 8
#define DGRPS (DI / SCAN_D)   // 192

// pass 1: per-segment local scan from h=0; emit h_end and decay product.
__global__ void __launch_bounds__(128) scan_pass1(const float* __restrict__ A_log)
{
    int t0 = blockIdx.x;
    const int dgrp = t0 % DGRPS; t0 /= DGRPS;
    const int s = t0 % SEG;
    const int b = t0 / SEG;
    const int d0 = dgrp * SCAN_D;
    const int tid  = threadIdx.x;
    const int lane = tid & 31;
    const int warp = tid >> 5;
    const int n    = lane & 15;
    const int dloc = (warp << 1) | (lane >> 4);
    const int d    = d0 + dloc;

    const float a = -__expf(A_log[d * NS + n]);

    __shared__ float dt_s[SCAN_T][SCAN_D];
    __shared__ float u_s [SCAN_T][SCAN_D];
    __shared__ float B_s [SCAN_T][16];

    float h = 0.f, cum = 1.f;

    for (int l0 = s * SLEN; l0 < (s + 1) * SLEN; l0 += SCAN_T) {
        for (int i = tid; i < SCAN_T * SCAN_D; i += 128) {
            int tt = i >> 3, dd = i & 7;
            size_t row = (size_t)(b * LL + l0 + tt);
            dt_s[tt][dd] = g_dt[row * DI + d0 + dd];
            u_s [tt][dd] = g_u [row * DI + d0 + dd];
        }
        for (int i = tid; i < SCAN_T * 16; i += 128) {
            int tt = i >> 4, nn = i & 15;
            B_s[tt][nn] = g_xdbl[(size_t)(b * LL + l0 + tt) * XP + RK + nn];
        }
        __syncthreads();
#pragma unroll 8
        for (int t = 0; t < SCAN_T; ++t) {
            float dtv = dt_s[t][dloc];
            float e = __expf(dtv * a);
            h = fmaf(h, e, dtv * u_s[t][dloc] * B_s[t][n]);
            cum *= e;
        }
        __syncthreads();
    }
    size_t off = ((size_t)(b * SEG + s) * DI + d) * NS + n;
    g_hend[off] = h;
    g_pend[off] = cum;
}

// mid: compose segment prefixes -> h_in per segment
__global__ void __launch_bounds__(256) scan_mid()
{
    int i = blockIdx.x * blockDim.x + threadIdx.x;
    if (i >= BB * DI * NS) return;
    int n = i & (NS - 1);
    int d = (i / NS) % DI;
    int b = i / (NS * DI);
    float h = 0.f;
#pragma unroll
    for (int s = 0; s < SEG; ++s) {
        size_t off = ((size_t)(b * SEG + s) * DI + d) * NS + n;
        g_hin[off] = h;
        h = fmaf(g_pend[off], h, g_hend[off]);
    }
}

// pass 3: re-run recurrence seeded with h_in; full y + skip + gate + fp16 split
__global__ void __launch_bounds__(128) scan_pass3(
    const float* __restrict__ A_log, const float* __restrict__ Dvec)
{
    int t0 = blockIdx.x;
    const int dgrp = t0 % DGRPS; t0 /= DGRPS;
    const int s = t0 % SEG;
    const int b = t0 / SEG;
    const int d0 = dgrp * SCAN_D;
    const int tid  = threadIdx.x;
    const int lane = tid & 31;
    const int warp = tid >> 5;
    const int n    = lane & 15;
    const int dloc = (warp << 1) | (lane >> 4);
    const int d    = d0 + dloc;

    const float a = -__expf(A_log[d * NS + n]);

    __shared__ float dt_s[SCAN_T][SCAN_D];
    __shared__ float u_s [SCAN_T][SCAN_D];
    __shared__ float z_s [SCAN_T][SCAN_D];
    __shared__ float B_s [SCAN_T][16];
    __shared__ float C_s [SCAN_T][16];
    __shared__ float yb  [SCAN_T][SCAN_D];

    float h = g_hin[((size_t)(b * SEG + s) * DI + d) * NS + n];

    for (int l0 = s * SLEN; l0 < (s + 1) * SLEN; l0 += SCAN_T) {
        for (int i = tid; i < SCAN_T * SCAN_D; i += 128) {
            int tt = i >> 3, dd = i & 7;
            size_t row = (size_t)(b * LL + l0 + tt);
            dt_s[tt][dd] = g_dt[row * DI + d0 + dd];
            u_s [tt][dd] = g_u [row * DI + d0 + dd];
            z_s [tt][dd] = g_xz[row * (2 * DI) + DI + d0 + dd];
        }
        for (int i = tid; i < SCAN_T * 16; i += 128) {
            int tt = i >> 4, nn = i & 15;
            size_t row = (size_t)(b * LL + l0 + tt);
            B_s[tt][nn] = g_xdbl[row * XP + RK + nn];
            C_s[tt][nn] = g_xdbl[row * XP + RK + NS + nn];
        }
        __syncthreads();

#pragma unroll 8
        for (int t = 0; t < SCAN_T; ++t) {
            float dtv = dt_s[t][dloc];
            h = fmaf(h, __expf(dtv * a), dtv * u_s[t][dloc] * B_s[t][n]);
            float p = h * C_s[t][n];
            p += __shfl_xor_sync(0xffffffffu, p, 8);
            p += __shfl_xor_sync(0xffffffffu, p, 4);
            p += __shfl_xor_sync(0xffffffffu, p, 2);
            p += __shfl_xor_sync(0xffffffffu, p, 1);
            if (n == 0) yb[t][dloc] = p;
        }
        __syncthreads();

        for (int i = tid; i < SCAN_T * SCAN_D; i += 128) {
            int tt = i >> 3, dd = i & 7;
            size_t row = (size_t)(b * LL + l0 + tt);
            float zz = z_s[tt][dd];
            float sz = zz / (1.f + __expf(-zz));
            float yv = fmaf(u_s[tt][dd], Dvec[d0 + dd], yb[tt][dd]) * sz;
            __half hv = __float2half(yv);
            __half lv = __float2half(yv - __half2float(hv));
            g_ah[row * DI + d0 + dd] = hv;
            g_al[row * DI + d0 + dd] = lv;
        }
        __syncthreads();
    }
}

// ---------------------------------------------------------------------------
// residual + LayerNorm over DM=768 (sums both out_proj partials)
// ---------------------------------------------------------------------------
__global__ void __launch_bounds__(256) resid_ln(
    const float* __restrict__ x, const float* __restrict__ w,
    const float* __restrict__ bln, float* __restrict__ out)
{
    const int row = blockIdx.x;
    const float* o1 = g_ob  + (size_t)row * DM;
    const float* o2 = g_ob2 + (size_t)row * DM;
    const float* xr = x     + (size_t)row * DM;

    float v[3];
    float s = 0.f, ss = 0.f;
#pragma unroll
    for (int i = 0; i < 3; ++i) {
        int c = threadIdx.x + i * 256;
        v[i] = o1[c] + o2[c] + xr[c];
        s += v[i];
        ss += v[i] * v[i];
    }
#pragma unroll
    for (int off = 16; off; off >>= 1) {
        s  += __shfl_xor_sync(0xffffffffu, s,  off);
        ss += __shfl_xor_sync(0xffffffffu, ss, off);
    }
    __shared__ float sbuf[16];
    int warp = threadIdx.x >> 5, lane = threadIdx.x & 31;
    if (lane == 0) { sbuf[warp] = s; sbuf[8 + warp] = ss; }
    __syncthreads();
    float S = 0.f, SS = 0.f;
#pragma unroll
    for (int i = 0; i < 8; ++i) { S += sbuf[i]; SS += sbuf[8 + i]; }
    float mean = S * (1.f / DM);
    float var  = SS * (1.f / DM) - mean * mean;
    float rstd = rsqrtf(var + 1e-5f);
#pragma unroll
    for (int i = 0; i < 3; ++i) {
        int c = threadIdx.x + i * 256;
        out[(size_t)row * DM + c] = (v[i] - mean) * rstd * w[c] + bln[c];
    }
}

// ---------------------------------------------------------------------------
extern "C" void kernel_launch(void* const* d_in, const int* in_sizes, int n_in,
                              void* d_out, int out_size)
{
    const float* x       = (const float*)d_in[0];
    const float* in_w    = (const float*)d_in[1];
    const float* conv_w  = (const float*)d_in[2];
    const float* conv_b  = (const float*)d_in[3];
    const float* xproj_w = (const float*)d_in[4];
    const float* dt_w    = (const float*)d_in[5];
    const float* dt_b    = (const float*)d_in[6];
    const float* A_log   = (const float*)d_in[7];
    const float* Dv      = (const float*)d_in[8];
    const float* out_w   = (const float*)d_in[9];
    const float* ln_w    = (const float*)d_in[10];
    const float* ln_b    = (const float*)d_in[11];
    float* out = (float*)d_out;

    float *p_xz, *p_ob, *p_ob2;
    cudaGetSymbolAddress((void**)&p_xz,  g_xz);
    cudaGetSymbolAddress((void**)&p_ob,  g_ob);
    cudaGetSymbolAddress((void**)&p_ob2, g_ob2);
    __half *p_ah, *p_al, *p_bh, *p_bh2;
    cudaGetSymbolAddress((void**)&p_ah,  g_ah);
    cudaGetSymbolAddress((void**)&p_al,  g_al);
    cudaGetSymbolAddress((void**)&p_bh,  g_bh);
    cudaGetSymbolAddress((void**)&p_bh2, g_bh2);

    cudaFuncSetAttribute(gemm_f16, cudaFuncAttributeMaxDynamicSharedMemorySize,
                         GEMM_SMEM);

    // (1) split x -> A hi/lo
    {
        int n4 = MROWS * DM / 4;
        split_kernel<<<(n4 + 255) / 256, 256>>>(
            (const float4*)x, (uint2*)p_ah, (uint2*)p_al, n4);
    }
    // (2) convert in_proj_w
    {
        int n4 = 2 * DI * DM / 4;
        convert_kernel<<<(n4 + 255) / 256, 256>>>(
            (const float4*)in_w, (uint2*)p_bh, n4);
    }
    // (3) convert out_proj_w
    {
        int n4 = DM * DI / 4;
        convert_kernel<<<(n4 + 255) / 256, 256>>>(
            (const float4*)out_w, (uint2*)p_bh2, n4);
    }

    // (4) in_proj GEMM: [4096, 3072]
    gemm_f16<<<dim3((2 * DI) / BN, MROWS / BM, 1), 256, GEMM_SMEM>>>(
        p_ah, p_al, p_bh, p_xz, p_xz, MROWS, 2 * DI, DM, DM);

    // (5) conv + silu
    conv_silu_kernel<<<(MROWS * DI + 255) / 256, 256>>>(conv_w, conv_b);

    // (6,7) x_proj
    gemm_xproj_part<<<dim3(MROWS / 32, 4), 256>>>(xproj_w);
    {
        int n4 = MROWS * XP / 4;
        xproj_reduce<<<(n4 + 255) / 256, 256>>>(n4);
    }

    // (8) dt_proj
    dtproj_softplus<<<dim3(MROWS / 64, DI / 128), 256>>>(dt_w, dt_b);

    // (9) segmented scan
    scan_pass1<<<BB * SEG * DGRPS, 128>>>(A_log);
    scan_mid<<<(BB * DI * NS + 255) / 256, 256>>>();
    scan_pass3<<<BB * SEG * DGRPS, 128>>>(A_log, Dv);

    // (10) out_proj GEMM split-K x2: [4096, 768], K=768 per half
    gemm_f16<<<dim3(DM / BN, MROWS / BM, 2), 256, GEMM_SMEM>>>(
        p_ah, p_al, p_bh2, p_ob, p_ob2, MROWS, DM, DI / 2, DI);

    // (11) residual + LayerNorm
    resid_ln<<<MROWS, 256>>>(x, ln_w, ln_b, out);
}